// round 14
// baseline (speedup 1.0000x reference)
#include <cuda_runtime.h>
#include <cuda_bf16.h>
#include <cuda_fp16.h>
#include <cstdint>
#include <math.h>

// ---------------- problem constants ----------------
#define SEQ   2048
#define HID   2048
#define NH    16
#define NKV   2
#define HD    256
#define MAXS  4096
#define RD    64
#define GROUPS 8
#define ATT_SCALE 0.0625f
#define EPSV  1e-6f
#define NQKV  9216

// ---------------- scratch ----------------
__device__ __align__(1024) float g_qkv  [(size_t)SEQ * NQKV];
__device__ __align__(1024) float g_scores[(size_t)NH * SEQ * SEQ];

__device__ __align__(1024) __half g_hid  [(size_t)SEQ * HID];
__device__ __align__(1024) __half g_wqkv [(size_t)NQKV * HID];
__device__ __align__(1024) __half g_ow   [(size_t)HID * NH*HD];
__device__ __align__(1024) __half g_q_h  [(size_t)NH*SEQ*HD], g_q_l[(size_t)NH*SEQ*HD];
__device__ __align__(1024) __half g_k    [(size_t)NKV*SEQ*HD];
__device__ __align__(1024) __half g_vT   [(size_t)NKV*HD*SEQ];
__device__ __align__(1024) __half g_p    [(size_t)NH*SEQ*SEQ];
__device__ __align__(1024) __half g_gt   [(size_t)SEQ * NH*HD];

// ---------------- PTX helpers ----------------
__device__ __forceinline__ uint32_t smem_u32(const void* p) {
    uint32_t a;
    asm("{ .reg .u64 t; cvta.to.shared.u64 t, %1; cvt.u32.u64 %0, t; }" : "=r"(a) : "l"(p));
    return a;
}
#define CP_ASYNC16(dst, src) \
    asm volatile("cp.async.cg.shared.global [%0], [%1], 16;" :: "r"(dst), "l"(src) : "memory")
#define CP_COMMIT() asm volatile("cp.async.commit_group;" ::: "memory")
#define CP_WAIT(n)  asm volatile("cp.async.wait_group %0;" :: "n"(n) : "memory")

#define LDSM_X4(r0, r1, r2, r3, addr) \
    asm volatile("ldmatrix.sync.aligned.m8n8.x4.shared.b16 {%0,%1,%2,%3}, [%4];" \
        : "=r"(r0), "=r"(r1), "=r"(r2), "=r"(r3) : "r"(addr))

#define MMA_F16(d, a, b0v, b1v) \
    asm volatile("mma.sync.aligned.m16n8k16.row.col.f32.f16.f16.f32 " \
        "{%0,%1,%2,%3}, {%4,%5,%6,%7}, {%8,%9}, {%0,%1,%2,%3};" \
        : "+f"((d)[0]), "+f"((d)[1]), "+f"((d)[2]), "+f"((d)[3]) \
        : "r"((a)[0]), "r"((a)[1]), "r"((a)[2]), "r"((a)[3]), "r"(b0v), "r"(b1v))

// ---------------- pack helpers ----------------
__device__ __forceinline__ uint32_t packh2(float a, float b) {
    __half2 h = __floats2half2_rn(a, b);
    return *reinterpret_cast<uint32_t*>(&h);
}
__device__ __forceinline__ uint32_t packh_hi2(float a, float b, float& la, float& lb) {
    __half ha = __float2half_rn(a), hb = __float2half_rn(b);
    la = a - __half2float(ha);
    lb = b - __half2float(hb);
    __half2 h2 = __halves2half2(ha, hb);
    return *reinterpret_cast<uint32_t*>(&h2);
}

// ---------------- fp16 1-term GEMM, 128x256 tile, 512 thr, 3-stage ----------------
// C = alpha * A * B^T ; stage = A 16K | B 32K = 48KB, 3 stages (144KB).
// mode 0 plain; 2 causal K-limit. Batch via bz.
// GATED=true: epilogue writes fp16 gOut = acc * sigmoid(gate slice of gQkv); C unused.
template<bool GATED>
__global__ __launch_bounds__(512, 1)
void gemm_1t_wide(const uint16_t* __restrict__ A, const uint16_t* __restrict__ B,
                  float* __restrict__ C,
                  int K, int lda, int ldb, int ldc,
                  long long sA, long long sB, long long sC, int bDiv,
                  float alpha, int mode,
                  const float* __restrict__ gQkv, __half* __restrict__ gOut)
{
    constexpr uint32_t STG = 49152u;

    const int bx = blockIdx.x, by = blockIdx.y, bz = blockIdx.z;
    const int Keff = (mode == 2) ? min(K, (by + 1) * 128) : K;
    const int nch = Keff >> 6;

    extern __shared__ char smem[];
    const uint32_t sb = smem_u32(smem);

    const uint16_t* pA = A + (size_t)bz * sA;
    const uint16_t* pB = B + (size_t)(bz / bDiv) * sB;
    const int rm = by * 128, rn = bx * 256;
    const int tid = threadIdx.x, lane = tid & 31, wid = tid >> 5;
    const int wm = wid >> 2, wn = wid & 3;   // 4x4 warp grid, warp tile 32x64

    float acc[2][8][4];
    #pragma unroll
    for (int mt = 0; mt < 2; ++mt)
        #pragma unroll
        for (int nt = 0; nt < 8; ++nt)
            #pragma unroll
            for (int r = 0; r < 4; ++r) acc[mt][nt][r] = 0.f;

    auto issue = [&](int ch) {
        const uint32_t dbase = sb + (uint32_t)(ch % 3) * STG;
        const int kt = ch << 6;
        #pragma unroll
        for (int i = 0; i < 2; ++i) {        // A: 128 rows
            const int u = tid + i * 512;
            const int r = u >> 3, c = u & 7;
            const uint16_t* s = pA + (size_t)(rm + r) * lda + kt + c * 8;
            const uint32_t d = dbase + (uint32_t)(r * 128 + ((c * 16) ^ ((r & 7) << 4)));
            CP_ASYNC16(d, (const void*)s);
        }
        #pragma unroll
        for (int i = 0; i < 4; ++i) {        // B: 256 rows
            const int u = tid + i * 512;
            const int r = u >> 3, c = u & 7;
            const uint16_t* s = pB + (size_t)(rn + r) * ldb + kt + c * 8;
            const uint32_t d = dbase + 16384u + (uint32_t)(r * 128 + ((c * 16) ^ ((r & 7) << 4)));
            CP_ASYNC16(d, (const void*)s);
        }
        CP_COMMIT();
    };

    issue(0);
    if (nch > 1) issue(1);
    for (int ch = 0; ch < nch; ++ch) {
        if (ch + 1 < nch) { CP_WAIT(1); }
        else              { CP_WAIT(0); }
        __syncthreads();
        if (ch + 2 < nch) issue(ch + 2);

        const uint32_t b0 = sb + (uint32_t)(ch % 3) * STG;

        #pragma unroll
        for (int ks = 0; ks < 4; ++ks) {
            const uint32_t colk = (uint32_t)(ks * 32 + ((lane >> 4) << 4));
            uint32_t ah[2][4], bh[4][4];
            #pragma unroll
            for (int mt = 0; mt < 2; ++mt) {
                const int row = wm * 32 + mt * 16 + (lane & 15);
                const uint32_t a0 = b0 + (uint32_t)(row * 128) + (colk ^ ((row & 7) << 4));
                LDSM_X4(ah[mt][0], ah[mt][1], ah[mt][2], ah[mt][3], a0);
            }
            #pragma unroll
            for (int pr = 0; pr < 4; ++pr) {
                const int row = wn * 64 + pr * 16 + (lane & 15);
                const uint32_t a0 = b0 + 16384u + (uint32_t)(row * 128) + (colk ^ ((row & 7) << 4));
                LDSM_X4(bh[pr][0], bh[pr][1], bh[pr][2], bh[pr][3], a0);
            }
            #pragma unroll
            for (int mt = 0; mt < 2; ++mt) {
                #pragma unroll
                for (int nt = 0; nt < 8; ++nt) {
                    const uint32_t b0v = bh[nt >> 1][nt & 1];
                    const uint32_t b1v = bh[nt >> 1][(nt & 1) + 2];
                    MMA_F16(acc[mt][nt], ah[mt], b0v, b1v);
                }
            }
        }
    }

    if (GATED) {
        #pragma unroll
        for (int mt = 0; mt < 2; ++mt) {
            #pragma unroll
            for (int nt = 0; nt < 8; ++nt) {
                const int row = rm + wm * 32 + mt * 16 + (lane >> 2);
                const int col = rn + wn * 64 + nt * 8 + (lane & 3) * 2;
                #pragma unroll
                for (int rr = 0; rr < 2; ++rr) {
                    const int r2 = row + rr * 8;
                    float a0 = acc[mt][nt][rr * 2 + 0];
                    float a1 = acc[mt][nt][rr * 2 + 1];
                    float2 g = *reinterpret_cast<const float2*>(
                        gQkv + (size_t)r2 * NQKV + bz * 512 + 256 + col);
                    float o0 = a0 * (1.f / (1.f + __expf(-g.x)));
                    float o1 = a1 * (1.f / (1.f + __expf(-g.y)));
                    *reinterpret_cast<uint32_t*>(
                        gOut + (size_t)r2 * (NH * HD) + bz * HD + col) = packh2(o0, o1);
                }
            }
        }
    } else {
        float* pC = C + (size_t)bz * sC;
        #pragma unroll
        for (int mt = 0; mt < 2; ++mt) {
            #pragma unroll
            for (int nt = 0; nt < 8; ++nt) {
                const int row = rm + wm * 32 + mt * 16 + (lane >> 2);
                const int col = rn + wn * 64 + nt * 8 + (lane & 3) * 2;
                float2 v0 = { acc[mt][nt][0] * alpha, acc[mt][nt][1] * alpha };
                float2 v1 = { acc[mt][nt][2] * alpha, acc[mt][nt][3] * alpha };
                *reinterpret_cast<float2*>(&pC[(size_t)row * ldc + col])       = v0;
                *reinterpret_cast<float2*>(&pC[(size_t)(row + 8) * ldc + col]) = v1;
            }
        }
    }
}

// ---------------- fp16 2-term GEMM, 128x128 tile, 256 thr (scores) ----------
// C = alpha * (Ah+Al) * Bh^T ; stage = Ah 16K | Al 16K | B 16K = 48KB, 2 stages.
// mode 1: causal block-skip.
__global__ __launch_bounds__(256, 2)
void gemm_2t(const uint16_t* __restrict__ Ah, const uint16_t* __restrict__ Al,
             const uint16_t* __restrict__ Bh,
             float* __restrict__ C,
             int K, int lda, int ldb, int ldc,
             long long sA, long long sB, long long sC, int bDiv,
             float alpha, int mode)
{
    constexpr uint32_t STG = 49152u;

    const int bx = blockIdx.x, by = blockIdx.y, bz = blockIdx.z;
    if (mode == 1 && bx > by) return;
    const int Keff = (mode == 2) ? min(K, (by + 1) * 128) : K;
    const int nch = Keff >> 6;

    extern __shared__ char smem[];
    const uint32_t sb = smem_u32(smem);

    const uint16_t* pAh = Ah + (size_t)bz * sA;
    const uint16_t* pAl = Al + (size_t)bz * sA;
    const uint16_t* pB  = Bh + (size_t)(bz / bDiv) * sB;
    const int rm = by * 128, rn = bx * 128;

    const int tid = threadIdx.x, lane = tid & 31, wid = tid >> 5;
    const int wm = wid >> 1, wn = wid & 1;   // 4x2 warp grid, warp tile 32x64

    float acc[2][8][4];
    #pragma unroll
    for (int mt = 0; mt < 2; ++mt)
        #pragma unroll
        for (int nt = 0; nt < 8; ++nt)
            #pragma unroll
            for (int r = 0; r < 4; ++r) acc[mt][nt][r] = 0.f;

    auto issue = [&](int ch) {
        const uint32_t dbase = sb + (uint32_t)(ch & 1) * STG;
        const int kt = ch << 6;
        #pragma unroll
        for (int p = 0; p < 3; ++p) {
            const uint16_t* sp = (p == 0) ? pAh : (p == 1) ? pAl : pB;
            const int rbase = (p < 2) ? rm : rn;
            const int ld = (p < 2) ? lda : ldb;
            #pragma unroll
            for (int i = 0; i < 4; ++i) {
                const int u = tid + i * 256;
                const int r = u >> 3, c = u & 7;
                const uint16_t* s = sp + (size_t)(rbase + r) * ld + kt + c * 8;
                const uint32_t d = dbase + (uint32_t)(p * 16384 + r * 128 +
                                   ((c * 16) ^ ((r & 7) << 4)));
                CP_ASYNC16(d, (const void*)s);
            }
        }
        CP_COMMIT();
    };

    issue(0);
    for (int ch = 0; ch < nch; ++ch) {
        CP_WAIT(0);
        __syncthreads();
        if (ch + 1 < nch) issue(ch + 1);

        const uint32_t b0 = sb + (uint32_t)(ch & 1) * STG;

        #pragma unroll
        for (int ks = 0; ks < 4; ++ks) {
            const uint32_t colk = (uint32_t)(ks * 32 + ((lane >> 4) << 4));
            uint32_t ah[2][4], alr[2][4], bh[4][4];
            #pragma unroll
            for (int mt = 0; mt < 2; ++mt) {
                const int row = wm * 32 + mt * 16 + (lane & 15);
                const uint32_t a0 = b0 + (uint32_t)(row * 128) + (colk ^ ((row & 7) << 4));
                LDSM_X4(ah [mt][0], ah [mt][1], ah [mt][2], ah [mt][3], a0);
                LDSM_X4(alr[mt][0], alr[mt][1], alr[mt][2], alr[mt][3], a0 + 16384u);
            }
            #pragma unroll
            for (int pr = 0; pr < 4; ++pr) {
                const int row = wn * 64 + pr * 16 + (lane & 15);
                const uint32_t a0 = b0 + 32768u + (uint32_t)(row * 128) + (colk ^ ((row & 7) << 4));
                LDSM_X4(bh[pr][0], bh[pr][1], bh[pr][2], bh[pr][3], a0);
            }
            #pragma unroll
            for (int term = 0; term < 2; ++term) {
                #pragma unroll
                for (int mt = 0; mt < 2; ++mt) {
                    #pragma unroll
                    for (int nt = 0; nt < 8; ++nt) {
                        const uint32_t* af = (term == 1) ? alr[mt] : ah[mt];
                        const uint32_t b0v = bh[nt >> 1][nt & 1];
                        const uint32_t b1v = bh[nt >> 1][(nt & 1) + 2];
                        MMA_F16(acc[mt][nt], af, b0v, b1v);
                    }
                }
            }
        }
    }

    float* pC = C + (size_t)bz * sC;
    #pragma unroll
    for (int mt = 0; mt < 2; ++mt) {
        #pragma unroll
        for (int nt = 0; nt < 8; ++nt) {
            const int row = rm + wm * 32 + mt * 16 + (lane >> 2);
            const int col = rn + wn * 64 + nt * 8 + (lane & 3) * 2;
            float2 v0 = { acc[mt][nt][0] * alpha, acc[mt][nt][1] * alpha };
            float2 v1 = { acc[mt][nt][2] * alpha, acc[mt][nt][3] * alpha };
            *reinterpret_cast<float2*>(&pC[(size_t)row * ldc + col])       = v0;
            *reinterpret_cast<float2*>(&pC[(size_t)(row + 8) * ldc + col]) = v1;
        }
    }
}

// ---------------- weight split: all weights -> single fp16 plane ----------------
__global__ void split_w_kernel(const float* __restrict__ qw, const float* __restrict__ kw,
                               const float* __restrict__ vw, const float* __restrict__ ow,
                               __half* __restrict__ wqkv, __half* __restrict__ owh)
{
    size_t i = (size_t)blockIdx.x * blockDim.x + threadIdx.x;
    if (i >= 6815744u) return;
    const float* src; size_t loc; __half* dst;
    if (i < 4194304u)      { src = qw; loc = i;            dst = wqkv; }
    else if (i < 4456448u) { src = kw; loc = i - 4194304u; dst = wqkv + 16777216u; }
    else if (i < 4718592u) { src = vw; loc = i - 4456448u; dst = wqkv + 17825792u; }
    else                   { src = ow; loc = i - 4718592u; dst = owh; }
    float4 v = reinterpret_cast<const float4*>(src)[loc];
    uint2 hh = { packh2(v.x, v.y), packh2(v.z, v.w) };
    reinterpret_cast<uint2*>(dst)[loc] = hh;
}

// ---------------- activation convert: hidden -> single fp16 plane ----------------
__global__ void split_a_kernel(const float* __restrict__ x, __half* __restrict__ h)
{
    size_t i = (size_t)blockIdx.x * blockDim.x + threadIdx.x;
    if (i >= 1048576u) return;
    float4 v = reinterpret_cast<const float4*>(x)[i];
    uint2 hh = { packh2(v.x, v.y), packh2(v.z, v.w) };
    reinterpret_cast<uint2*>(h)[i] = hh;
}

// ---------------- block reduce ----------------
__device__ __forceinline__ float blk_reduce(float v, bool do_max, float* sred,
                                            int tid, int lane, int wid) {
    #pragma unroll
    for (int o = 16; o > 0; o >>= 1) {
        float t = __shfl_xor_sync(0xffffffffu, v, o);
        v = do_max ? fmaxf(v, t) : (v + t);
    }
    if (lane == 0) sred[wid] = v;
    __syncthreads();
    if (tid == 0) {
        float r = sred[0];
        #pragma unroll
        for (int w = 1; w < 8; ++w) r = do_max ? fmaxf(r, sred[w]) : (r + sred[w]);
        sred[8] = r;
    }
    __syncthreads();
    float r = sred[8];
    __syncthreads();
    return r;
}

// ---------------- RMSNorm + RoPE for Q -> fp16 hi/lo ----------------
__global__ __launch_bounds__(256)
void q_norm_rope_kernel(const float* __restrict__ qkv,
                        const float* __restrict__ cosb, const float* __restrict__ sinb,
                        const float* __restrict__ qw,
                        __half* __restrict__ qh, __half* __restrict__ ql)
{
    const int s = blockIdx.x, h = blockIdx.y, d = threadIdx.x;
    const int lane = d & 31, wid = d >> 5;
    float x = qkv[(size_t)s * NQKV + h * 512 + d];
    __shared__ float sred[9];
    __shared__ float xs[256];
    float r = blk_reduce(x * x, false, sred, d, lane, wid);
    r = rsqrtf(r * (1.f / HD) + EPSV);
    float xn = x * r * (1.f + qw[d]);
    xs[d] = xn;
    __syncthreads();
    float o = xn;
    if (d < RD) {
        float rot = (d < RD / 2) ? -xs[d + RD / 2] : xs[d - RD / 2];
        o = xn * cosb[(size_t)s * RD + d] + rot * sinb[(size_t)s * RD + d];
    }
    size_t idx = ((size_t)h * SEQ + s) * HD + d;
    __half hv = __float2half_rn(o);
    qh[idx] = hv;
    ql[idx] = __float2half_rn(o - __half2float(hv));
}

// ---------------- RMSNorm + RoPE for K; caches + fp16 planes ----------------
__global__ __launch_bounds__(256)
void kv_norm_rope_kernel(const float* __restrict__ qkv,
                         const float* __restrict__ cosb, const float* __restrict__ sinb,
                         const float* __restrict__ kw,
                         float* __restrict__ kcache, float* __restrict__ vcache,
                         __half* __restrict__ kplane, __half* __restrict__ vT)
{
    const int s = blockIdx.x, kv = blockIdx.y, d = threadIdx.x;
    const int lane = d & 31, wid = d >> 5;
    float x = qkv[(size_t)s * NQKV + 8192 + kv * 256 + d];
    float v = qkv[(size_t)s * NQKV + 8704 + kv * 256 + d];
    __shared__ float sred[9];
    __shared__ float xs[256];
    float r = blk_reduce(x * x, false, sred, d, lane, wid);
    r = rsqrtf(r * (1.f / HD) + EPSV);
    float xn = x * r * (1.f + kw[d]);
    xs[d] = xn;
    __syncthreads();
    float o = xn;
    if (d < RD) {
        float rot = (d < RD / 2) ? -xs[d + RD / 2] : xs[d - RD / 2];
        o = xn * cosb[(size_t)s * RD + d] + rot * sinb[(size_t)s * RD + d];
    }
    size_t cidx = ((size_t)kv * MAXS + s) * HD + d;
    kcache[cidx] = o;
    vcache[cidx] = v;
    kplane[((size_t)kv * SEQ + s) * HD + d] = __float2half_rn(o);
    vT[((size_t)kv * HD + d) * SEQ + s] = __float2half_rn(v);
}

// ---------------- zero pad caches rows SEQ..MAXS ----------------
__global__ void zero_pad_kernel(float* __restrict__ kcache, float* __restrict__ vcache)
{
    size_t idx = (size_t)blockIdx.x * blockDim.x + threadIdx.x;
    const size_t per_kv = (size_t)(MAXS - SEQ) * HD;
    if (idx >= (size_t)NKV * per_kv) return;
    size_t kv = idx / per_kv, rem = idx - kv * per_kv;
    size_t off = kv * (size_t)MAXS * HD + (size_t)SEQ * HD + rem;
    kcache[off] = 0.f;
    vcache[off] = 0.f;
}

// ---------------- causal softmax -> single fp16 P plane ----------------
__global__ __launch_bounds__(256)
void softmax_kernel(const float* __restrict__ scores, __half* __restrict__ ph)
{
    const int i = blockIdx.x, h = blockIdx.y, tid = threadIdx.x;
    const int lane = tid & 31, wid = tid >> 5;
    const float* row = scores + ((size_t)h * SEQ + i) * SEQ;
    __half* prh = ph + ((size_t)h * SEQ + i) * SEQ;
    const int n = i + 1;
    const int end = ((i >> 7) + 1) << 7;
    const int j0 = tid * 8;
    __shared__ float sred[9];

    float v[8];
    if (j0 < end) {
        float4 a = *reinterpret_cast<const float4*>(row + j0);
        float4 b = *reinterpret_cast<const float4*>(row + j0 + 4);
        v[0]=a.x; v[1]=a.y; v[2]=a.z; v[3]=a.w;
        v[4]=b.x; v[5]=b.y; v[6]=b.z; v[7]=b.w;
    } else {
        #pragma unroll
        for (int e = 0; e < 8; ++e) v[e] = -1e30f;
    }

    float m = -1e30f;
    #pragma unroll
    for (int e = 0; e < 8; ++e) if (j0 + e < n) m = fmaxf(m, v[e]);
    m = blk_reduce(m, true, sred, tid, lane, wid);

    float sum = 0.f;
    #pragma unroll
    for (int e = 0; e < 8; ++e) {
        float p = (j0 + e < n) ? __expf(v[e] - m) : 0.f;
        v[e] = p;
        sum += p;
    }
    sum = blk_reduce(sum, false, sred, tid, lane, wid);
    const float inv = 1.f / sum;

    if (j0 < end) {
        uint4 hh;
        hh.x = packh2(v[0]*inv, v[1]*inv);
        hh.y = packh2(v[2]*inv, v[3]*inv);
        hh.z = packh2(v[4]*inv, v[5]*inv);
        hh.w = packh2(v[6]*inv, v[7]*inv);
        *reinterpret_cast<uint4*>(prh + j0) = hh;
    }
}

// ---------------- launch ----------------
extern "C" void kernel_launch(void* const* d_in, const int* in_sizes, int n_in,
                              void* d_out, int out_size)
{
    const float* hidden = (const float*)d_in[0];
    const float* cosb   = (const float*)d_in[1];
    const float* sinb   = (const float*)d_in[2];
    const float* q_w    = (const float*)d_in[3];
    const float* k_w    = (const float*)d_in[4];
    const float* v_w    = (const float*)d_in[5];
    const float* o_w    = (const float*)d_in[6];
    const float* qnw    = (const float*)d_in[7];
    const float* knw    = (const float*)d_in[8];

    float* hidden_out = (float*)d_out;
    float* kcache = hidden_out + (size_t)SEQ * HID;
    float* vcache = kcache + (size_t)NKV * MAXS * HD;

    float *qkv, *sc;
    __half *hid, *wqkv, *owh, *kpl, *vT, *qh, *ql, *ph, *gt;
    cudaGetSymbolAddress((void**)&qkv, g_qkv);
    cudaGetSymbolAddress((void**)&sc, g_scores);
    cudaGetSymbolAddress((void**)&hid, g_hid);
    cudaGetSymbolAddress((void**)&wqkv, g_wqkv);
    cudaGetSymbolAddress((void**)&owh, g_ow);
    cudaGetSymbolAddress((void**)&qh, g_q_h);   cudaGetSymbolAddress((void**)&ql, g_q_l);
    cudaGetSymbolAddress((void**)&kpl, g_k);
    cudaGetSymbolAddress((void**)&vT, g_vT);
    cudaGetSymbolAddress((void**)&ph, g_p);
    cudaGetSymbolAddress((void**)&gt, g_gt);

    cudaFuncSetAttribute(gemm_1t_wide<false>, cudaFuncAttributeMaxDynamicSharedMemorySize, 147456);
    cudaFuncSetAttribute(gemm_1t_wide<true>,  cudaFuncAttributeMaxDynamicSharedMemorySize, 147456);
    cudaFuncSetAttribute(gemm_2t,             cudaFuncAttributeMaxDynamicSharedMemorySize, 98304);

    dim3 blk(256);

    // 1) cache zero-pad
    zero_pad_kernel<<<(unsigned)(((size_t)NKV * (MAXS - SEQ) * HD + 255) / 256), blk>>>(kcache, vcache);
    // 2) weight split
    split_w_kernel<<<26624, blk>>>(q_w, k_w, v_w, o_w, wqkv, owh);
    // 3) activation -> fp16
    split_a_kernel<<<4096, blk>>>(hidden, hid);

    // 4) fused qkv projection [2048 x 9216], fp16 1-term wide (lean instantiation)
    gemm_1t_wide<false><<<dim3(NQKV/256, SEQ/128, 1), dim3(512), 147456>>>(
        (const uint16_t*)hid, (const uint16_t*)wqkv, qkv,
        HID, HID, HID, NQKV, 0, 0, 0, 1, 1.f, 0, nullptr, nullptr);

    // 5-6) norms + rope + caches
    q_norm_rope_kernel<<<dim3(SEQ, NH), blk>>>(qkv, cosb, sinb, qnw, qh, ql);
    kv_norm_rope_kernel<<<dim3(SEQ, NKV), blk>>>(qkv, cosb, sinb, knw,
                                                 kcache, vcache, kpl, vT);

    // 7) scores = Q @ K^T * scale (causal block skip), fp16 Q-2term / K-1term
    gemm_2t<<<dim3(SEQ/128, SEQ/128, NH), blk, 98304>>>(
        (const uint16_t*)qh, (const uint16_t*)ql, (const uint16_t*)kpl,
        sc, HD, HD, HD, SEQ,
        (long long)SEQ * HD, (long long)SEQ * HD, (long long)SEQ * SEQ, GROUPS,
        ATT_SCALE, 1);

    // 8) softmax -> single fp16 P plane
    softmax_kernel<<<dim3(SEQ, NH), blk>>>(sc, ph);

    // 9) attn = P @ V (causal K limit) + fused sigmoid gating -> fp16 gt
    gemm_1t_wide<true><<<dim3(HD/256, SEQ/128, NH), dim3(512), 147456>>>(
        (const uint16_t*)ph, (const uint16_t*)vT, nullptr,
        SEQ, SEQ, SEQ, HD,
        (long long)SEQ * SEQ, (long long)HD * SEQ, 0, GROUPS,
        1.f, 2, qkv, gt);

    // 10) hidden_out = gated @ o_w^T, fp16 1-term wide (lean instantiation)
    gemm_1t_wide<false><<<dim3(HID/256, SEQ/128, 1), dim3(512), 147456>>>(
        (const uint16_t*)gt, (const uint16_t*)owh, hidden_out,
        NH*HD, NH*HD, NH*HD, HID, 0, 0, 0, 1, 1.f, 0, nullptr, nullptr);
}

// round 15
// speedup vs baseline: 1.0528x; 1.0528x over previous
#include <cuda_runtime.h>
#include <cuda_bf16.h>
#include <cuda_fp16.h>
#include <cstdint>
#include <math.h>

// ---------------- problem constants ----------------
#define SEQ   2048
#define HID   2048
#define NH    16
#define NKV   2
#define HD    256
#define MAXS  4096
#define RD    64
#define GROUPS 8
#define ATT_SCALE 0.0625f
#define EPSV  1e-6f
#define NQKV  9216

// ---------------- scratch ----------------
__device__ __align__(1024) float g_qkv  [(size_t)SEQ * NQKV];
__device__ __align__(1024) float g_scores[(size_t)NH * SEQ * SEQ];
__device__ __align__(1024) float g_attn [(size_t)NH * SEQ * HD];      // split-K partial 0
__device__ __align__(1024) float g_attn2[(size_t)NH * SEQ * HD];      // split-K partial 1

__device__ __align__(1024) __half g_hid  [(size_t)SEQ * HID];
__device__ __align__(1024) __half g_wqkv [(size_t)NQKV * HID];
__device__ __align__(1024) __half g_ow   [(size_t)HID * NH*HD];
__device__ __align__(1024) __half g_q_h  [(size_t)NH*SEQ*HD], g_q_l[(size_t)NH*SEQ*HD];
__device__ __align__(1024) __half g_k    [(size_t)NKV*SEQ*HD];
__device__ __align__(1024) __half g_vT   [(size_t)NKV*HD*SEQ];
__device__ __align__(1024) __half g_p    [(size_t)NH*SEQ*SEQ];
__device__ __align__(1024) __half g_gt   [(size_t)SEQ * NH*HD];

// ---------------- PTX helpers ----------------
__device__ __forceinline__ uint32_t smem_u32(const void* p) {
    uint32_t a;
    asm("{ .reg .u64 t; cvta.to.shared.u64 t, %1; cvt.u32.u64 %0, t; }" : "=r"(a) : "l"(p));
    return a;
}
#define CP_ASYNC16(dst, src) \
    asm volatile("cp.async.cg.shared.global [%0], [%1], 16;" :: "r"(dst), "l"(src) : "memory")
#define CP_COMMIT() asm volatile("cp.async.commit_group;" ::: "memory")
#define CP_WAIT(n)  asm volatile("cp.async.wait_group %0;" :: "n"(n) : "memory")

#define LDSM_X4(r0, r1, r2, r3, addr) \
    asm volatile("ldmatrix.sync.aligned.m8n8.x4.shared.b16 {%0,%1,%2,%3}, [%4];" \
        : "=r"(r0), "=r"(r1), "=r"(r2), "=r"(r3) : "r"(addr))

#define MMA_F16(d, a, b0v, b1v) \
    asm volatile("mma.sync.aligned.m16n8k16.row.col.f32.f16.f16.f32 " \
        "{%0,%1,%2,%3}, {%4,%5,%6,%7}, {%8,%9}, {%0,%1,%2,%3};" \
        : "+f"((d)[0]), "+f"((d)[1]), "+f"((d)[2]), "+f"((d)[3]) \
        : "r"((a)[0]), "r"((a)[1]), "r"((a)[2]), "r"((a)[3]), "r"(b0v), "r"(b1v))

// ---------------- pack helpers ----------------
__device__ __forceinline__ uint32_t packh2(float a, float b) {
    __half2 h = __floats2half2_rn(a, b);
    return *reinterpret_cast<uint32_t*>(&h);
}
__device__ __forceinline__ uint32_t packh_hi2(float a, float b, float& la, float& lb) {
    __half ha = __float2half_rn(a), hb = __float2half_rn(b);
    la = a - __half2float(ha);
    lb = b - __half2float(hb);
    __half2 h2 = __halves2half2(ha, hb);
    return *reinterpret_cast<uint32_t*>(&h2);
}

// ---------------- fp16 1-term GEMM, 128x256 tile, 512 thr, 3-stage (R11 lean) ----
// C = alpha * A * B^T ; stage = A 16K | B 32K = 48KB, 3 stages (144KB). mode 0 plain.
__global__ __launch_bounds__(512, 1)
void gemm_1t_wide(const uint16_t* __restrict__ A, const uint16_t* __restrict__ B,
                  float* __restrict__ C,
                  int K, int lda, int ldb, int ldc,
                  long long sA, long long sB, long long sC, int bDiv,
                  float alpha, int mode)
{
    constexpr uint32_t STG = 49152u;

    const int bx = blockIdx.x, by = blockIdx.y, bz = blockIdx.z;
    const int Keff = (mode == 2) ? min(K, (by + 1) * 128) : K;
    const int nch = Keff >> 6;

    extern __shared__ char smem[];
    const uint32_t sb = smem_u32(smem);

    const uint16_t* pA = A + (size_t)bz * sA;
    const uint16_t* pB = B + (size_t)(bz / bDiv) * sB;
    const int rm = by * 128, rn = bx * 256;
    const int tid = threadIdx.x, lane = tid & 31, wid = tid >> 5;
    const int wm = wid >> 2, wn = wid & 3;

    float acc[2][8][4];
    #pragma unroll
    for (int mt = 0; mt < 2; ++mt)
        #pragma unroll
        for (int nt = 0; nt < 8; ++nt)
            #pragma unroll
            for (int r = 0; r < 4; ++r) acc[mt][nt][r] = 0.f;

    auto issue = [&](int ch) {
        const uint32_t dbase = sb + (uint32_t)(ch % 3) * STG;
        const int kt = ch << 6;
        #pragma unroll
        for (int i = 0; i < 2; ++i) {
            const int u = tid + i * 512;
            const int r = u >> 3, c = u & 7;
            const uint16_t* s = pA + (size_t)(rm + r) * lda + kt + c * 8;
            const uint32_t d = dbase + (uint32_t)(r * 128 + ((c * 16) ^ ((r & 7) << 4)));
            CP_ASYNC16(d, (const void*)s);
        }
        #pragma unroll
        for (int i = 0; i < 4; ++i) {
            const int u = tid + i * 512;
            const int r = u >> 3, c = u & 7;
            const uint16_t* s = pB + (size_t)(rn + r) * ldb + kt + c * 8;
            const uint32_t d = dbase + 16384u + (uint32_t)(r * 128 + ((c * 16) ^ ((r & 7) << 4)));
            CP_ASYNC16(d, (const void*)s);
        }
        CP_COMMIT();
    };

    issue(0);
    if (nch > 1) issue(1);
    for (int ch = 0; ch < nch; ++ch) {
        if (ch + 1 < nch) { CP_WAIT(1); }
        else              { CP_WAIT(0); }
        __syncthreads();
        if (ch + 2 < nch) issue(ch + 2);

        const uint32_t b0 = sb + (uint32_t)(ch % 3) * STG;

        #pragma unroll
        for (int ks = 0; ks < 4; ++ks) {
            const uint32_t colk = (uint32_t)(ks * 32 + ((lane >> 4) << 4));
            uint32_t ah[2][4], bh[4][4];
            #pragma unroll
            for (int mt = 0; mt < 2; ++mt) {
                const int row = wm * 32 + mt * 16 + (lane & 15);
                const uint32_t a0 = b0 + (uint32_t)(row * 128) + (colk ^ ((row & 7) << 4));
                LDSM_X4(ah[mt][0], ah[mt][1], ah[mt][2], ah[mt][3], a0);
            }
            #pragma unroll
            for (int pr = 0; pr < 4; ++pr) {
                const int row = wn * 64 + pr * 16 + (lane & 15);
                const uint32_t a0 = b0 + 16384u + (uint32_t)(row * 128) + (colk ^ ((row & 7) << 4));
                LDSM_X4(bh[pr][0], bh[pr][1], bh[pr][2], bh[pr][3], a0);
            }
            #pragma unroll
            for (int mt = 0; mt < 2; ++mt) {
                #pragma unroll
                for (int nt = 0; nt < 8; ++nt) {
                    const uint32_t b0v = bh[nt >> 1][nt & 1];
                    const uint32_t b1v = bh[nt >> 1][(nt & 1) + 2];
                    MMA_F16(acc[mt][nt], ah[mt], b0v, b1v);
                }
            }
        }
    }

    float* pC = C + (size_t)bz * sC;
    #pragma unroll
    for (int mt = 0; mt < 2; ++mt) {
        #pragma unroll
        for (int nt = 0; nt < 8; ++nt) {
            const int row = rm + wm * 32 + mt * 16 + (lane >> 2);
            const int col = rn + wn * 64 + nt * 8 + (lane & 3) * 2;
            float2 v0 = { acc[mt][nt][0] * alpha, acc[mt][nt][1] * alpha };
            float2 v1 = { acc[mt][nt][2] * alpha, acc[mt][nt][3] * alpha };
            *reinterpret_cast<float2*>(&pC[(size_t)row * ldc + col])       = v0;
            *reinterpret_cast<float2*>(&pC[(size_t)(row + 8) * ldc + col]) = v1;
        }
    }
}

// ---------------- PV split-K GEMM (clone; causal, split-K=2, by reversed) ------
// grid (1, 16, NH*2); bz = head*2 + kz. Writes fp32 partial to C + head*sC
// (kz=0) or C2 + head*sC (kz=1). K range: [kz*1024, min((by+1)*128, kz*1024+1024)).
__global__ __launch_bounds__(512, 1)
void gemm_pv(const uint16_t* __restrict__ A, const uint16_t* __restrict__ B,
             float* __restrict__ C, float* __restrict__ C2,
             int lda, int ldb, int ldc,
             long long sA, long long sB, long long sC)
{
    constexpr uint32_t STG = 49152u;

    const int bx = blockIdx.x;
    const int by = (int)gridDim.y - 1 - (int)blockIdx.y;   // big K blocks first
    const int bz = blockIdx.z;
    const int head = bz >> 1, kz = bz & 1;

    const int Keff = min(SEQ, (by + 1) * 128);
    const int kbeg = kz << 10;
    const int kend = min(Keff, kbeg + 1024);
    if (kbeg >= kend) return;
    const int ch0 = kbeg >> 6;
    const int nch = (kend - kbeg) >> 6;

    extern __shared__ char smem[];
    const uint32_t sb = smem_u32(smem);

    const uint16_t* pA = A + (size_t)head * sA;
    const uint16_t* pB = B + (size_t)(head / GROUPS) * sB;
    const int rm = by * 128, rn = bx * 256;
    const int tid = threadIdx.x, lane = tid & 31, wid = tid >> 5;
    const int wm = wid >> 2, wn = wid & 3;

    float acc[2][8][4];
    #pragma unroll
    for (int mt = 0; mt < 2; ++mt)
        #pragma unroll
        for (int nt = 0; nt < 8; ++nt)
            #pragma unroll
            for (int r = 0; r < 4; ++r) acc[mt][nt][r] = 0.f;

    auto issue = [&](int cc) {
        const uint32_t dbase = sb + (uint32_t)(cc % 3) * STG;
        const int kt = (ch0 + cc) << 6;
        #pragma unroll
        for (int i = 0; i < 2; ++i) {
            const int u = tid + i * 512;
            const int r = u >> 3, c = u & 7;
            const uint16_t* s = pA + (size_t)(rm + r) * lda + kt + c * 8;
            const uint32_t d = dbase + (uint32_t)(r * 128 + ((c * 16) ^ ((r & 7) << 4)));
            CP_ASYNC16(d, (const void*)s);
        }
        #pragma unroll
        for (int i = 0; i < 4; ++i) {
            const int u = tid + i * 512;
            const int r = u >> 3, c = u & 7;
            const uint16_t* s = pB + (size_t)(rn + r) * ldb + kt + c * 8;
            const uint32_t d = dbase + 16384u + (uint32_t)(r * 128 + ((c * 16) ^ ((r & 7) << 4)));
            CP_ASYNC16(d, (const void*)s);
        }
        CP_COMMIT();
    };

    issue(0);
    if (nch > 1) issue(1);
    for (int cc = 0; cc < nch; ++cc) {
        if (cc + 1 < nch) { CP_WAIT(1); }
        else              { CP_WAIT(0); }
        __syncthreads();
        if (cc + 2 < nch) issue(cc + 2);

        const uint32_t b0 = sb + (uint32_t)(cc % 3) * STG;

        #pragma unroll
        for (int ks = 0; ks < 4; ++ks) {
            const uint32_t colk = (uint32_t)(ks * 32 + ((lane >> 4) << 4));
            uint32_t ah[2][4], bh[4][4];
            #pragma unroll
            for (int mt = 0; mt < 2; ++mt) {
                const int row = wm * 32 + mt * 16 + (lane & 15);
                const uint32_t a0 = b0 + (uint32_t)(row * 128) + (colk ^ ((row & 7) << 4));
                LDSM_X4(ah[mt][0], ah[mt][1], ah[mt][2], ah[mt][3], a0);
            }
            #pragma unroll
            for (int pr = 0; pr < 4; ++pr) {
                const int row = wn * 64 + pr * 16 + (lane & 15);
                const uint32_t a0 = b0 + 16384u + (uint32_t)(row * 128) + (colk ^ ((row & 7) << 4));
                LDSM_X4(bh[pr][0], bh[pr][1], bh[pr][2], bh[pr][3], a0);
            }
            #pragma unroll
            for (int mt = 0; mt < 2; ++mt) {
                #pragma unroll
                for (int nt = 0; nt < 8; ++nt) {
                    const uint32_t b0v = bh[nt >> 1][nt & 1];
                    const uint32_t b1v = bh[nt >> 1][(nt & 1) + 2];
                    MMA_F16(acc[mt][nt], ah[mt], b0v, b1v);
                }
            }
        }
    }

    float* pC = (kz ? C2 : C) + (size_t)head * sC;
    #pragma unroll
    for (int mt = 0; mt < 2; ++mt) {
        #pragma unroll
        for (int nt = 0; nt < 8; ++nt) {
            const int row = rm + wm * 32 + mt * 16 + (lane >> 2);
            const int col = rn + wn * 64 + nt * 8 + (lane & 3) * 2;
            float2 v0 = { acc[mt][nt][0], acc[mt][nt][1] };
            float2 v1 = { acc[mt][nt][2], acc[mt][nt][3] };
            *reinterpret_cast<float2*>(&pC[(size_t)row * ldc + col])       = v0;
            *reinterpret_cast<float2*>(&pC[(size_t)(row + 8) * ldc + col]) = v1;
        }
    }
}

// ---------------- fp16 2-term GEMM, 128x128 tile, 256 thr (scores) ----------
__global__ __launch_bounds__(256, 2)
void gemm_2t(const uint16_t* __restrict__ Ah, const uint16_t* __restrict__ Al,
             const uint16_t* __restrict__ Bh,
             float* __restrict__ C,
             int K, int lda, int ldb, int ldc,
             long long sA, long long sB, long long sC, int bDiv,
             float alpha, int mode)
{
    constexpr uint32_t STG = 49152u;

    const int bx = blockIdx.x, by = blockIdx.y, bz = blockIdx.z;
    if (mode == 1 && bx > by) return;
    const int Keff = (mode == 2) ? min(K, (by + 1) * 128) : K;
    const int nch = Keff >> 6;

    extern __shared__ char smem[];
    const uint32_t sb = smem_u32(smem);

    const uint16_t* pAh = Ah + (size_t)bz * sA;
    const uint16_t* pAl = Al + (size_t)bz * sA;
    const uint16_t* pB  = Bh + (size_t)(bz / bDiv) * sB;
    const int rm = by * 128, rn = bx * 128;

    const int tid = threadIdx.x, lane = tid & 31, wid = tid >> 5;
    const int wm = wid >> 1, wn = wid & 1;

    float acc[2][8][4];
    #pragma unroll
    for (int mt = 0; mt < 2; ++mt)
        #pragma unroll
        for (int nt = 0; nt < 8; ++nt)
            #pragma unroll
            for (int r = 0; r < 4; ++r) acc[mt][nt][r] = 0.f;

    auto issue = [&](int ch) {
        const uint32_t dbase = sb + (uint32_t)(ch & 1) * STG;
        const int kt = ch << 6;
        #pragma unroll
        for (int p = 0; p < 3; ++p) {
            const uint16_t* sp = (p == 0) ? pAh : (p == 1) ? pAl : pB;
            const int rbase = (p < 2) ? rm : rn;
            const int ld = (p < 2) ? lda : ldb;
            #pragma unroll
            for (int i = 0; i < 4; ++i) {
                const int u = tid + i * 256;
                const int r = u >> 3, c = u & 7;
                const uint16_t* s = sp + (size_t)(rbase + r) * ld + kt + c * 8;
                const uint32_t d = dbase + (uint32_t)(p * 16384 + r * 128 +
                                   ((c * 16) ^ ((r & 7) << 4)));
                CP_ASYNC16(d, (const void*)s);
            }
        }
        CP_COMMIT();
    };

    issue(0);
    for (int ch = 0; ch < nch; ++ch) {
        CP_WAIT(0);
        __syncthreads();
        if (ch + 1 < nch) issue(ch + 1);

        const uint32_t b0 = sb + (uint32_t)(ch & 1) * STG;

        #pragma unroll
        for (int ks = 0; ks < 4; ++ks) {
            const uint32_t colk = (uint32_t)(ks * 32 + ((lane >> 4) << 4));
            uint32_t ah[2][4], alr[2][4], bh[4][4];
            #pragma unroll
            for (int mt = 0; mt < 2; ++mt) {
                const int row = wm * 32 + mt * 16 + (lane & 15);
                const uint32_t a0 = b0 + (uint32_t)(row * 128) + (colk ^ ((row & 7) << 4));
                LDSM_X4(ah [mt][0], ah [mt][1], ah [mt][2], ah [mt][3], a0);
                LDSM_X4(alr[mt][0], alr[mt][1], alr[mt][2], alr[mt][3], a0 + 16384u);
            }
            #pragma unroll
            for (int pr = 0; pr < 4; ++pr) {
                const int row = wn * 64 + pr * 16 + (lane & 15);
                const uint32_t a0 = b0 + 32768u + (uint32_t)(row * 128) + (colk ^ ((row & 7) << 4));
                LDSM_X4(bh[pr][0], bh[pr][1], bh[pr][2], bh[pr][3], a0);
            }
            #pragma unroll
            for (int term = 0; term < 2; ++term) {
                #pragma unroll
                for (int mt = 0; mt < 2; ++mt) {
                    #pragma unroll
                    for (int nt = 0; nt < 8; ++nt) {
                        const uint32_t* af = (term == 1) ? alr[mt] : ah[mt];
                        const uint32_t b0v = bh[nt >> 1][nt & 1];
                        const uint32_t b1v = bh[nt >> 1][(nt & 1) + 2];
                        MMA_F16(acc[mt][nt], af, b0v, b1v);
                    }
                }
            }
        }
    }

    float* pC = C + (size_t)bz * sC;
    #pragma unroll
    for (int mt = 0; mt < 2; ++mt) {
        #pragma unroll
        for (int nt = 0; nt < 8; ++nt) {
            const int row = rm + wm * 32 + mt * 16 + (lane >> 2);
            const int col = rn + wn * 64 + nt * 8 + (lane & 3) * 2;
            float2 v0 = { acc[mt][nt][0] * alpha, acc[mt][nt][1] * alpha };
            float2 v1 = { acc[mt][nt][2] * alpha, acc[mt][nt][3] * alpha };
            *reinterpret_cast<float2*>(&pC[(size_t)row * ldc + col])       = v0;
            *reinterpret_cast<float2*>(&pC[(size_t)(row + 8) * ldc + col]) = v1;
        }
    }
}

// ---------------- fused fp32->fp16 convert: hidden + all weights ----------------
// quads: hid [0,1048576) qw [.,5242880) kw [.,5505024) vw [.,5767168) ow [.,7864320)
__global__ void split_all_kernel(const float* __restrict__ hid4, const float* __restrict__ qw,
                                 const float* __restrict__ kw, const float* __restrict__ vw,
                                 const float* __restrict__ ow,
                                 __half* __restrict__ hidh, __half* __restrict__ wqkv,
                                 __half* __restrict__ owh)
{
    size_t i = (size_t)blockIdx.x * blockDim.x + threadIdx.x;
    if (i >= 7864320u) return;
    const float* src; size_t loc; __half* dst;
    if (i < 1048576u)      { src = hid4; loc = i;            dst = hidh; }
    else if (i < 5242880u) { src = qw;   loc = i - 1048576u; dst = wqkv; }
    else if (i < 5505024u) { src = kw;   loc = i - 5242880u; dst = wqkv + 16777216u; }
    else if (i < 5767168u) { src = vw;   loc = i - 5505024u; dst = wqkv + 17825792u; }
    else                   { src = ow;   loc = i - 5767168u; dst = owh; }
    float4 v = reinterpret_cast<const float4*>(src)[loc];
    uint2 hh = { packh2(v.x, v.y), packh2(v.z, v.w) };
    reinterpret_cast<uint2*>(dst)[loc] = hh;
}

// ---------------- block reduce ----------------
__device__ __forceinline__ float blk_reduce(float v, bool do_max, float* sred,
                                            int tid, int lane, int wid) {
    #pragma unroll
    for (int o = 16; o > 0; o >>= 1) {
        float t = __shfl_xor_sync(0xffffffffu, v, o);
        v = do_max ? fmaxf(v, t) : (v + t);
    }
    if (lane == 0) sred[wid] = v;
    __syncthreads();
    if (tid == 0) {
        float r = sred[0];
        #pragma unroll
        for (int w = 1; w < 8; ++w) r = do_max ? fmaxf(r, sred[w]) : (r + sred[w]);
        sred[8] = r;
    }
    __syncthreads();
    float r = sred[8];
    __syncthreads();
    return r;
}

// ---------------- RMSNorm + RoPE for Q -> fp16 hi/lo ----------------
__global__ __launch_bounds__(256)
void q_norm_rope_kernel(const float* __restrict__ qkv,
                        const float* __restrict__ cosb, const float* __restrict__ sinb,
                        const float* __restrict__ qw,
                        __half* __restrict__ qh, __half* __restrict__ ql)
{
    const int s = blockIdx.x, h = blockIdx.y, d = threadIdx.x;
    const int lane = d & 31, wid = d >> 5;
    float x = qkv[(size_t)s * NQKV + h * 512 + d];
    __shared__ float sred[9];
    __shared__ float xs[256];
    float r = blk_reduce(x * x, false, sred, d, lane, wid);
    r = rsqrtf(r * (1.f / HD) + EPSV);
    float xn = x * r * (1.f + qw[d]);
    xs[d] = xn;
    __syncthreads();
    float o = xn;
    if (d < RD) {
        float rot = (d < RD / 2) ? -xs[d + RD / 2] : xs[d - RD / 2];
        o = xn * cosb[(size_t)s * RD + d] + rot * sinb[(size_t)s * RD + d];
    }
    size_t idx = ((size_t)h * SEQ + s) * HD + d;
    __half hv = __float2half_rn(o);
    qh[idx] = hv;
    ql[idx] = __float2half_rn(o - __half2float(hv));
}

// ---------------- RMSNorm + RoPE for K; caches + fp16 planes ----------------
__global__ __launch_bounds__(256)
void kv_norm_rope_kernel(const float* __restrict__ qkv,
                         const float* __restrict__ cosb, const float* __restrict__ sinb,
                         const float* __restrict__ kw,
                         float* __restrict__ kcache, float* __restrict__ vcache,
                         __half* __restrict__ kplane, __half* __restrict__ vT)
{
    const int s = blockIdx.x, kv = blockIdx.y, d = threadIdx.x;
    const int lane = d & 31, wid = d >> 5;
    float x = qkv[(size_t)s * NQKV + 8192 + kv * 256 + d];
    float v = qkv[(size_t)s * NQKV + 8704 + kv * 256 + d];
    __shared__ float sred[9];
    __shared__ float xs[256];
    float r = blk_reduce(x * x, false, sred, d, lane, wid);
    r = rsqrtf(r * (1.f / HD) + EPSV);
    float xn = x * r * (1.f + kw[d]);
    xs[d] = xn;
    __syncthreads();
    float o = xn;
    if (d < RD) {
        float rot = (d < RD / 2) ? -xs[d + RD / 2] : xs[d - RD / 2];
        o = xn * cosb[(size_t)s * RD + d] + rot * sinb[(size_t)s * RD + d];
    }
    size_t cidx = ((size_t)kv * MAXS + s) * HD + d;
    kcache[cidx] = o;
    vcache[cidx] = v;
    kplane[((size_t)kv * SEQ + s) * HD + d] = __float2half_rn(o);
    vT[((size_t)kv * HD + d) * SEQ + s] = __float2half_rn(v);
}

// ---------------- zero pad caches rows SEQ..MAXS ----------------
__global__ void zero_pad_kernel(float* __restrict__ kcache, float* __restrict__ vcache)
{
    size_t idx = (size_t)blockIdx.x * blockDim.x + threadIdx.x;
    const size_t per_kv = (size_t)(MAXS - SEQ) * HD;
    if (idx >= (size_t)NKV * per_kv) return;
    size_t kv = idx / per_kv, rem = idx - kv * per_kv;
    size_t off = kv * (size_t)MAXS * HD + (size_t)SEQ * HD + rem;
    kcache[off] = 0.f;
    vcache[off] = 0.f;
}

// ---------------- causal softmax -> single fp16 P plane ----------------
__global__ __launch_bounds__(256)
void softmax_kernel(const float* __restrict__ scores, __half* __restrict__ ph)
{
    const int i = blockIdx.x, h = blockIdx.y, tid = threadIdx.x;
    const int lane = tid & 31, wid = tid >> 5;
    const float* row = scores + ((size_t)h * SEQ + i) * SEQ;
    __half* prh = ph + ((size_t)h * SEQ + i) * SEQ;
    const int n = i + 1;
    const int end = ((i >> 7) + 1) << 7;
    const int j0 = tid * 8;
    __shared__ float sred[9];

    float v[8];
    if (j0 < end) {
        float4 a = *reinterpret_cast<const float4*>(row + j0);
        float4 b = *reinterpret_cast<const float4*>(row + j0 + 4);
        v[0]=a.x; v[1]=a.y; v[2]=a.z; v[3]=a.w;
        v[4]=b.x; v[5]=b.y; v[6]=b.z; v[7]=b.w;
    } else {
        #pragma unroll
        for (int e = 0; e < 8; ++e) v[e] = -1e30f;
    }

    float m = -1e30f;
    #pragma unroll
    for (int e = 0; e < 8; ++e) if (j0 + e < n) m = fmaxf(m, v[e]);
    m = blk_reduce(m, true, sred, tid, lane, wid);

    float sum = 0.f;
    #pragma unroll
    for (int e = 0; e < 8; ++e) {
        float p = (j0 + e < n) ? __expf(v[e] - m) : 0.f;
        v[e] = p;
        sum += p;
    }
    sum = blk_reduce(sum, false, sred, tid, lane, wid);
    const float inv = 1.f / sum;

    if (j0 < end) {
        uint4 hh;
        hh.x = packh2(v[0]*inv, v[1]*inv);
        hh.y = packh2(v[2]*inv, v[3]*inv);
        hh.z = packh2(v[4]*inv, v[5]*inv);
        hh.w = packh2(v[6]*inv, v[7]*inv);
        *reinterpret_cast<uint4*>(prh + j0) = hh;
    }
}

// ---------------- gating: sum split-K partials, sigmoid gate -> fp16 plane -----
__global__ void gate_kernel(const float* __restrict__ attn, const float* __restrict__ attn2,
                            const float* __restrict__ qkv, __half* __restrict__ gh)
{
    size_t idx = (size_t)blockIdx.x * blockDim.x + threadIdx.x;
    if (idx >= (size_t)SEQ * NH * HD / 4) return;
    int s = (int)(idx >> 10);
    int r = (int)(idx & 1023);
    int h = r >> 6, dq = (r & 63) * 4;
    size_t aoff = ((size_t)h * SEQ + s) * HD + dq;
    float4 a = *reinterpret_cast<const float4*>(&attn[aoff]);
    if (s >= 1024) {
        float4 a2 = *reinterpret_cast<const float4*>(&attn2[aoff]);
        a.x += a2.x; a.y += a2.y; a.z += a2.z; a.w += a2.w;
    }
    float4 g = *reinterpret_cast<const float4*>(&qkv[(size_t)s * NQKV + h * 512 + 256 + dq]);
    float o0 = a.x * (1.f / (1.f + __expf(-g.x)));
    float o1 = a.y * (1.f / (1.f + __expf(-g.y)));
    float o2 = a.z * (1.f / (1.f + __expf(-g.z)));
    float o3 = a.w * (1.f / (1.f + __expf(-g.w)));
    uint2 hh = { packh2(o0, o1), packh2(o2, o3) };
    size_t o = (size_t)s * (NH * HD) + h * HD + dq;
    *reinterpret_cast<uint2*>(gh + o) = hh;
}

// ---------------- launch ----------------
extern "C" void kernel_launch(void* const* d_in, const int* in_sizes, int n_in,
                              void* d_out, int out_size)
{
    const float* hidden = (const float*)d_in[0];
    const float* cosb   = (const float*)d_in[1];
    const float* sinb   = (const float*)d_in[2];
    const float* q_w    = (const float*)d_in[3];
    const float* k_w    = (const float*)d_in[4];
    const float* v_w    = (const float*)d_in[5];
    const float* o_w    = (const float*)d_in[6];
    const float* qnw    = (const float*)d_in[7];
    const float* knw    = (const float*)d_in[8];

    float* hidden_out = (float*)d_out;
    float* kcache = hidden_out + (size_t)SEQ * HID;
    float* vcache = kcache + (size_t)NKV * MAXS * HD;

    float *qkv, *sc, *at, *at2;
    __half *hid, *wqkv, *owh, *kpl, *vT, *qh, *ql, *ph, *gt;
    cudaGetSymbolAddress((void**)&qkv, g_qkv);
    cudaGetSymbolAddress((void**)&sc, g_scores);
    cudaGetSymbolAddress((void**)&at, g_attn);
    cudaGetSymbolAddress((void**)&at2, g_attn2);
    cudaGetSymbolAddress((void**)&hid, g_hid);
    cudaGetSymbolAddress((void**)&wqkv, g_wqkv);
    cudaGetSymbolAddress((void**)&owh, g_ow);
    cudaGetSymbolAddress((void**)&qh, g_q_h);   cudaGetSymbolAddress((void**)&ql, g_q_l);
    cudaGetSymbolAddress((void**)&kpl, g_k);
    cudaGetSymbolAddress((void**)&vT, g_vT);
    cudaGetSymbolAddress((void**)&ph, g_p);
    cudaGetSymbolAddress((void**)&gt, g_gt);

    cudaFuncSetAttribute(gemm_1t_wide, cudaFuncAttributeMaxDynamicSharedMemorySize, 147456);
    cudaFuncSetAttribute(gemm_pv,      cudaFuncAttributeMaxDynamicSharedMemorySize, 147456);
    cudaFuncSetAttribute(gemm_2t,      cudaFuncAttributeMaxDynamicSharedMemorySize, 98304);

    dim3 blk(256);

    // 1) cache zero-pad
    zero_pad_kernel<<<(unsigned)(((size_t)NKV * (MAXS - SEQ) * HD + 255) / 256), blk>>>(kcache, vcache);
    // 2) all fp32->fp16 converts in one launch
    split_all_kernel<<<30720, blk>>>(hidden, q_w, k_w, v_w, o_w, hid, wqkv, owh);

    // 3) fused qkv projection [2048 x 9216], fp16 1-term wide
    gemm_1t_wide<<<dim3(NQKV/256, SEQ/128, 1), dim3(512), 147456>>>(
        (const uint16_t*)hid, (const uint16_t*)wqkv, qkv,
        HID, HID, HID, NQKV, 0, 0, 0, 1, 1.f, 0);

    // 4-5) norms + rope + caches
    q_norm_rope_kernel<<<dim3(SEQ, NH), blk>>>(qkv, cosb, sinb, qnw, qh, ql);
    kv_norm_rope_kernel<<<dim3(SEQ, NKV), blk>>>(qkv, cosb, sinb, knw,
                                                 kcache, vcache, kpl, vT);

    // 6) scores = Q @ K^T * scale (causal block skip), fp16 Q-2term / K-1term
    gemm_2t<<<dim3(SEQ/128, SEQ/128, NH), blk, 98304>>>(
        (const uint16_t*)qh, (const uint16_t*)ql, (const uint16_t*)kpl,
        sc, HD, HD, HD, SEQ,
        (long long)SEQ * HD, (long long)SEQ * HD, (long long)SEQ * SEQ, GROUPS,
        ATT_SCALE, 1);

    // 7) softmax -> single fp16 P plane
    softmax_kernel<<<dim3(SEQ, NH), blk>>>(sc, ph);

    // 8) attn = P @ V, causal split-K=2, big blocks first
    gemm_pv<<<dim3(1, 16, NH * 2), dim3(512), 147456>>>(
        (const uint16_t*)ph, (const uint16_t*)vT, at, at2,
        SEQ, SEQ, HD,
        (long long)SEQ * SEQ, (long long)HD * SEQ, (long long)SEQ * HD);

    // 9) gating (sums split-K partials) -> fp16 plane
    gate_kernel<<<(unsigned)(((size_t)SEQ * NH * HD / 4 + 255) / 256), blk>>>(at, at2, qkv, gt);

    // 10) hidden_out = gated @ o_w^T, fp16 1-term wide
    gemm_1t_wide<<<dim3(HID/256, SEQ/128, 1), dim3(512), 147456>>>(
        (const uint16_t*)gt, (const uint16_t*)owh, hidden_out,
        NH*HD, NH*HD, NH*HD, HID, 0, 0, 0, 1, 1.f, 0);
}

// round 16
// speedup vs baseline: 1.0854x; 1.0310x over previous
#include <cuda_runtime.h>
#include <cuda_bf16.h>
#include <cuda_fp16.h>
#include <cstdint>
#include <math.h>

// ---------------- problem constants ----------------
#define SEQ   2048
#define HID   2048
#define NH    16
#define NKV   2
#define HD    256
#define MAXS  4096
#define RD    64
#define GROUPS 8
#define ATT_SCALE 0.0625f
#define EPSV  1e-6f
#define NQKV  9216

// ---------------- scratch ----------------
__device__ __align__(1024) float g_qkv  [(size_t)SEQ * NQKV];
__device__ __align__(1024) float g_scores[(size_t)NH * SEQ * SEQ];
__device__ __align__(1024) float g_attn [(size_t)NH * SEQ * HD];
__device__ __align__(1024) float g_attn2[(size_t)NH * SEQ * HD];

__device__ __align__(1024) __half g_hid  [(size_t)SEQ * HID];
__device__ __align__(1024) __half g_wqkv [(size_t)NQKV * HID];
__device__ __align__(1024) __half g_ow   [(size_t)HID * NH*HD];
__device__ __align__(1024) __half g_q_h  [(size_t)NH*SEQ*HD], g_q_l[(size_t)NH*SEQ*HD];
__device__ __align__(1024) __half g_k    [(size_t)NKV*SEQ*HD];
__device__ __align__(1024) __half g_vT   [(size_t)NKV*HD*SEQ];
__device__ __align__(1024) __half g_p    [(size_t)NH*SEQ*SEQ];
__device__ __align__(1024) __half g_gt   [(size_t)SEQ * NH*HD];

// ---------------- PTX helpers ----------------
__device__ __forceinline__ uint32_t smem_u32(const void* p) {
    uint32_t a;
    asm("{ .reg .u64 t; cvta.to.shared.u64 t, %1; cvt.u32.u64 %0, t; }" : "=r"(a) : "l"(p));
    return a;
}
#define CP_ASYNC16(dst, src) \
    asm volatile("cp.async.cg.shared.global [%0], [%1], 16;" :: "r"(dst), "l"(src) : "memory")
#define CP_COMMIT() asm volatile("cp.async.commit_group;" ::: "memory")
#define CP_WAIT(n)  asm volatile("cp.async.wait_group %0;" :: "n"(n) : "memory")

#define LDSM_X4(r0, r1, r2, r3, addr) \
    asm volatile("ldmatrix.sync.aligned.m8n8.x4.shared.b16 {%0,%1,%2,%3}, [%4];" \
        : "=r"(r0), "=r"(r1), "=r"(r2), "=r"(r3) : "r"(addr))

#define MMA_F16(d, a, b0v, b1v) \
    asm volatile("mma.sync.aligned.m16n8k16.row.col.f32.f16.f16.f32 " \
        "{%0,%1,%2,%3}, {%4,%5,%6,%7}, {%8,%9}, {%0,%1,%2,%3};" \
        : "+f"((d)[0]), "+f"((d)[1]), "+f"((d)[2]), "+f"((d)[3]) \
        : "r"((a)[0]), "r"((a)[1]), "r"((a)[2]), "r"((a)[3]), "r"(b0v), "r"(b1v))

// ---------------- pack helpers ----------------
__device__ __forceinline__ uint32_t packh2(float a, float b) {
    __half2 h = __floats2half2_rn(a, b);
    return *reinterpret_cast<uint32_t*>(&h);
}

// ---------------- fp16 1-term GEMM, 128x256 tile, 512 thr, 3-stage (R11 lean) ----
__global__ __launch_bounds__(512, 1)
void gemm_1t_wide(const uint16_t* __restrict__ A, const uint16_t* __restrict__ B,
                  float* __restrict__ C,
                  int K, int lda, int ldb, int ldc,
                  long long sA, long long sB, long long sC, int bDiv,
                  float alpha, int mode)
{
    constexpr uint32_t STG = 49152u;

    const int bx = blockIdx.x, by = blockIdx.y, bz = blockIdx.z;
    const int Keff = (mode == 2) ? min(K, (by + 1) * 128) : K;
    const int nch = Keff >> 6;

    extern __shared__ char smem[];
    const uint32_t sb = smem_u32(smem);

    const uint16_t* pA = A + (size_t)bz * sA;
    const uint16_t* pB = B + (size_t)(bz / bDiv) * sB;
    const int rm = by * 128, rn = bx * 256;
    const int tid = threadIdx.x, lane = tid & 31, wid = tid >> 5;
    const int wm = wid >> 2, wn = wid & 3;

    float acc[2][8][4];
    #pragma unroll
    for (int mt = 0; mt < 2; ++mt)
        #pragma unroll
        for (int nt = 0; nt < 8; ++nt)
            #pragma unroll
            for (int r = 0; r < 4; ++r) acc[mt][nt][r] = 0.f;

    auto issue = [&](int ch) {
        const uint32_t dbase = sb + (uint32_t)(ch % 3) * STG;
        const int kt = ch << 6;
        #pragma unroll
        for (int i = 0; i < 2; ++i) {
            const int u = tid + i * 512;
            const int r = u >> 3, c = u & 7;
            const uint16_t* s = pA + (size_t)(rm + r) * lda + kt + c * 8;
            const uint32_t d = dbase + (uint32_t)(r * 128 + ((c * 16) ^ ((r & 7) << 4)));
            CP_ASYNC16(d, (const void*)s);
        }
        #pragma unroll
        for (int i = 0; i < 4; ++i) {
            const int u = tid + i * 512;
            const int r = u >> 3, c = u & 7;
            const uint16_t* s = pB + (size_t)(rn + r) * ldb + kt + c * 8;
            const uint32_t d = dbase + 16384u + (uint32_t)(r * 128 + ((c * 16) ^ ((r & 7) << 4)));
            CP_ASYNC16(d, (const void*)s);
        }
        CP_COMMIT();
    };

    issue(0);
    if (nch > 1) issue(1);
    for (int ch = 0; ch < nch; ++ch) {
        if (ch + 1 < nch) { CP_WAIT(1); }
        else              { CP_WAIT(0); }
        __syncthreads();
        if (ch + 2 < nch) issue(ch + 2);

        const uint32_t b0 = sb + (uint32_t)(ch % 3) * STG;

        #pragma unroll
        for (int ks = 0; ks < 4; ++ks) {
            const uint32_t colk = (uint32_t)(ks * 32 + ((lane >> 4) << 4));
            uint32_t ah[2][4], bh[4][4];
            #pragma unroll
            for (int mt = 0; mt < 2; ++mt) {
                const int row = wm * 32 + mt * 16 + (lane & 15);
                const uint32_t a0 = b0 + (uint32_t)(row * 128) + (colk ^ ((row & 7) << 4));
                LDSM_X4(ah[mt][0], ah[mt][1], ah[mt][2], ah[mt][3], a0);
            }
            #pragma unroll
            for (int pr = 0; pr < 4; ++pr) {
                const int row = wn * 64 + pr * 16 + (lane & 15);
                const uint32_t a0 = b0 + 16384u + (uint32_t)(row * 128) + (colk ^ ((row & 7) << 4));
                LDSM_X4(bh[pr][0], bh[pr][1], bh[pr][2], bh[pr][3], a0);
            }
            #pragma unroll
            for (int mt = 0; mt < 2; ++mt) {
                #pragma unroll
                for (int nt = 0; nt < 8; ++nt) {
                    const uint32_t b0v = bh[nt >> 1][nt & 1];
                    const uint32_t b1v = bh[nt >> 1][(nt & 1) + 2];
                    MMA_F16(acc[mt][nt], ah[mt], b0v, b1v);
                }
            }
        }
    }

    float* pC = C + (size_t)bz * sC;
    #pragma unroll
    for (int mt = 0; mt < 2; ++mt) {
        #pragma unroll
        for (int nt = 0; nt < 8; ++nt) {
            const int row = rm + wm * 32 + mt * 16 + (lane >> 2);
            const int col = rn + wn * 64 + nt * 8 + (lane & 3) * 2;
            float2 v0 = { acc[mt][nt][0] * alpha, acc[mt][nt][1] * alpha };
            float2 v1 = { acc[mt][nt][2] * alpha, acc[mt][nt][3] * alpha };
            *reinterpret_cast<float2*>(&pC[(size_t)row * ldc + col])       = v0;
            *reinterpret_cast<float2*>(&pC[(size_t)(row + 8) * ldc + col]) = v1;
        }
    }
}

// ---------------- PV split-K GEMM (causal, split-K=2, by reversed) ------
__global__ __launch_bounds__(512, 1)
void gemm_pv(const uint16_t* __restrict__ A, const uint16_t* __restrict__ B,
             float* __restrict__ C, float* __restrict__ C2,
             int lda, int ldb, int ldc,
             long long sA, long long sB, long long sC)
{
    constexpr uint32_t STG = 49152u;

    const int bx = blockIdx.x;
    const int by = (int)gridDim.y - 1 - (int)blockIdx.y;
    const int bz = blockIdx.z;
    const int head = bz >> 1, kz = bz & 1;

    const int Keff = min(SEQ, (by + 1) * 128);
    const int kbeg = kz << 10;
    const int kend = min(Keff, kbeg + 1024);
    if (kbeg >= kend) return;
    const int ch0 = kbeg >> 6;
    const int nch = (kend - kbeg) >> 6;

    extern __shared__ char smem[];
    const uint32_t sb = smem_u32(smem);

    const uint16_t* pA = A + (size_t)head * sA;
    const uint16_t* pB = B + (size_t)(head / GROUPS) * sB;
    const int rm = by * 128, rn = bx * 256;
    const int tid = threadIdx.x, lane = tid & 31, wid = tid >> 5;
    const int wm = wid >> 2, wn = wid & 3;

    float acc[2][8][4];
    #pragma unroll
    for (int mt = 0; mt < 2; ++mt)
        #pragma unroll
        for (int nt = 0; nt < 8; ++nt)
            #pragma unroll
            for (int r = 0; r < 4; ++r) acc[mt][nt][r] = 0.f;

    auto issue = [&](int cc) {
        const uint32_t dbase = sb + (uint32_t)(cc % 3) * STG;
        const int kt = (ch0 + cc) << 6;
        #pragma unroll
        for (int i = 0; i < 2; ++i) {
            const int u = tid + i * 512;
            const int r = u >> 3, c = u & 7;
            const uint16_t* s = pA + (size_t)(rm + r) * lda + kt + c * 8;
            const uint32_t d = dbase + (uint32_t)(r * 128 + ((c * 16) ^ ((r & 7) << 4)));
            CP_ASYNC16(d, (const void*)s);
        }
        #pragma unroll
        for (int i = 0; i < 4; ++i) {
            const int u = tid + i * 512;
            const int r = u >> 3, c = u & 7;
            const uint16_t* s = pB + (size_t)(rn + r) * ldb + kt + c * 8;
            const uint32_t d = dbase + 16384u + (uint32_t)(r * 128 + ((c * 16) ^ ((r & 7) << 4)));
            CP_ASYNC16(d, (const void*)s);
        }
        CP_COMMIT();
    };

    issue(0);
    if (nch > 1) issue(1);
    for (int cc = 0; cc < nch; ++cc) {
        if (cc + 1 < nch) { CP_WAIT(1); }
        else              { CP_WAIT(0); }
        __syncthreads();
        if (cc + 2 < nch) issue(cc + 2);

        const uint32_t b0 = sb + (uint32_t)(cc % 3) * STG;

        #pragma unroll
        for (int ks = 0; ks < 4; ++ks) {
            const uint32_t colk = (uint32_t)(ks * 32 + ((lane >> 4) << 4));
            uint32_t ah[2][4], bh[4][4];
            #pragma unroll
            for (int mt = 0; mt < 2; ++mt) {
                const int row = wm * 32 + mt * 16 + (lane & 15);
                const uint32_t a0 = b0 + (uint32_t)(row * 128) + (colk ^ ((row & 7) << 4));
                LDSM_X4(ah[mt][0], ah[mt][1], ah[mt][2], ah[mt][3], a0);
            }
            #pragma unroll
            for (int pr = 0; pr < 4; ++pr) {
                const int row = wn * 64 + pr * 16 + (lane & 15);
                const uint32_t a0 = b0 + 16384u + (uint32_t)(row * 128) + (colk ^ ((row & 7) << 4));
                LDSM_X4(bh[pr][0], bh[pr][1], bh[pr][2], bh[pr][3], a0);
            }
            #pragma unroll
            for (int mt = 0; mt < 2; ++mt) {
                #pragma unroll
                for (int nt = 0; nt < 8; ++nt) {
                    const uint32_t b0v = bh[nt >> 1][nt & 1];
                    const uint32_t b1v = bh[nt >> 1][(nt & 1) + 2];
                    MMA_F16(acc[mt][nt], ah[mt], b0v, b1v);
                }
            }
        }
    }

    float* pC = (kz ? C2 : C) + (size_t)head * sC;
    #pragma unroll
    for (int mt = 0; mt < 2; ++mt) {
        #pragma unroll
        for (int nt = 0; nt < 8; ++nt) {
            const int row = rm + wm * 32 + mt * 16 + (lane >> 2);
            const int col = rn + wn * 64 + nt * 8 + (lane & 3) * 2;
            float2 v0 = { acc[mt][nt][0], acc[mt][nt][1] };
            float2 v1 = { acc[mt][nt][2], acc[mt][nt][3] };
            *reinterpret_cast<float2*>(&pC[(size_t)row * ldc + col])       = v0;
            *reinterpret_cast<float2*>(&pC[(size_t)(row + 8) * ldc + col]) = v1;
        }
    }
}

// ---------------- fp16 2-term GEMM, 128x128 tile, 256 thr (scores) ----------
__global__ __launch_bounds__(256, 2)
void gemm_2t(const uint16_t* __restrict__ Ah, const uint16_t* __restrict__ Al,
             const uint16_t* __restrict__ Bh,
             float* __restrict__ C,
             int K, int lda, int ldb, int ldc,
             long long sA, long long sB, long long sC, int bDiv,
             float alpha, int mode)
{
    constexpr uint32_t STG = 49152u;

    const int bx = blockIdx.x, by = blockIdx.y, bz = blockIdx.z;
    if (mode == 1 && bx > by) return;
    const int Keff = (mode == 2) ? min(K, (by + 1) * 128) : K;
    const int nch = Keff >> 6;

    extern __shared__ char smem[];
    const uint32_t sb = smem_u32(smem);

    const uint16_t* pAh = Ah + (size_t)bz * sA;
    const uint16_t* pAl = Al + (size_t)bz * sA;
    const uint16_t* pB  = Bh + (size_t)(bz / bDiv) * sB;
    const int rm = by * 128, rn = bx * 128;

    const int tid = threadIdx.x, lane = tid & 31, wid = tid >> 5;
    const int wm = wid >> 1, wn = wid & 1;

    float acc[2][8][4];
    #pragma unroll
    for (int mt = 0; mt < 2; ++mt)
        #pragma unroll
        for (int nt = 0; nt < 8; ++nt)
            #pragma unroll
            for (int r = 0; r < 4; ++r) acc[mt][nt][r] = 0.f;

    auto issue = [&](int ch) {
        const uint32_t dbase = sb + (uint32_t)(ch & 1) * STG;
        const int kt = ch << 6;
        #pragma unroll
        for (int p = 0; p < 3; ++p) {
            const uint16_t* sp = (p == 0) ? pAh : (p == 1) ? pAl : pB;
            const int rbase = (p < 2) ? rm : rn;
            const int ld = (p < 2) ? lda : ldb;
            #pragma unroll
            for (int i = 0; i < 4; ++i) {
                const int u = tid + i * 256;
                const int r = u >> 3, c = u & 7;
                const uint16_t* s = sp + (size_t)(rbase + r) * ld + kt + c * 8;
                const uint32_t d = dbase + (uint32_t)(p * 16384 + r * 128 +
                                   ((c * 16) ^ ((r & 7) << 4)));
                CP_ASYNC16(d, (const void*)s);
            }
        }
        CP_COMMIT();
    };

    issue(0);
    for (int ch = 0; ch < nch; ++ch) {
        CP_WAIT(0);
        __syncthreads();
        if (ch + 1 < nch) issue(ch + 1);

        const uint32_t b0 = sb + (uint32_t)(ch & 1) * STG;

        #pragma unroll
        for (int ks = 0; ks < 4; ++ks) {
            const uint32_t colk = (uint32_t)(ks * 32 + ((lane >> 4) << 4));
            uint32_t ah[2][4], alr[2][4], bh[4][4];
            #pragma unroll
            for (int mt = 0; mt < 2; ++mt) {
                const int row = wm * 32 + mt * 16 + (lane & 15);
                const uint32_t a0 = b0 + (uint32_t)(row * 128) + (colk ^ ((row & 7) << 4));
                LDSM_X4(ah [mt][0], ah [mt][1], ah [mt][2], ah [mt][3], a0);
                LDSM_X4(alr[mt][0], alr[mt][1], alr[mt][2], alr[mt][3], a0 + 16384u);
            }
            #pragma unroll
            for (int pr = 0; pr < 4; ++pr) {
                const int row = wn * 64 + pr * 16 + (lane & 15);
                const uint32_t a0 = b0 + 32768u + (uint32_t)(row * 128) + (colk ^ ((row & 7) << 4));
                LDSM_X4(bh[pr][0], bh[pr][1], bh[pr][2], bh[pr][3], a0);
            }
            #pragma unroll
            for (int term = 0; term < 2; ++term) {
                #pragma unroll
                for (int mt = 0; mt < 2; ++mt) {
                    #pragma unroll
                    for (int nt = 0; nt < 8; ++nt) {
                        const uint32_t* af = (term == 1) ? alr[mt] : ah[mt];
                        const uint32_t b0v = bh[nt >> 1][nt & 1];
                        const uint32_t b1v = bh[nt >> 1][(nt & 1) + 2];
                        MMA_F16(acc[mt][nt], af, b0v, b1v);
                    }
                }
            }
        }
    }

    float* pC = C + (size_t)bz * sC;
    #pragma unroll
    for (int mt = 0; mt < 2; ++mt) {
        #pragma unroll
        for (int nt = 0; nt < 8; ++nt) {
            const int row = rm + wm * 32 + mt * 16 + (lane >> 2);
            const int col = rn + wn * 64 + nt * 8 + (lane & 3) * 2;
            float2 v0 = { acc[mt][nt][0] * alpha, acc[mt][nt][1] * alpha };
            float2 v1 = { acc[mt][nt][2] * alpha, acc[mt][nt][3] * alpha };
            *reinterpret_cast<float2*>(&pC[(size_t)row * ldc + col])       = v0;
            *reinterpret_cast<float2*>(&pC[(size_t)(row + 8) * ldc + col]) = v1;
        }
    }
}

// ---------------- fused fp32->fp16 convert: hidden + all weights ----------------
__global__ void split_all_kernel(const float* __restrict__ hid4, const float* __restrict__ qw,
                                 const float* __restrict__ kw, const float* __restrict__ vw,
                                 const float* __restrict__ ow,
                                 __half* __restrict__ hidh, __half* __restrict__ wqkv,
                                 __half* __restrict__ owh)
{
    size_t i = (size_t)blockIdx.x * blockDim.x + threadIdx.x;
    if (i >= 7864320u) return;
    const float* src; size_t loc; __half* dst;
    if (i < 1048576u)      { src = hid4; loc = i;            dst = hidh; }
    else if (i < 5242880u) { src = qw;   loc = i - 1048576u; dst = wqkv; }
    else if (i < 5505024u) { src = kw;   loc = i - 5242880u; dst = wqkv + 16777216u; }
    else if (i < 5767168u) { src = vw;   loc = i - 5505024u; dst = wqkv + 17825792u; }
    else                   { src = ow;   loc = i - 5767168u; dst = owh; }
    float4 v = reinterpret_cast<const float4*>(src)[loc];
    uint2 hh = { packh2(v.x, v.y), packh2(v.z, v.w) };
    reinterpret_cast<uint2*>(dst)[loc] = hh;
}

// ---------------- block reduce (kv_norm / softmax) ----------------
__device__ __forceinline__ float blk_reduce(float v, bool do_max, float* sred,
                                            int tid, int lane, int wid) {
    #pragma unroll
    for (int o = 16; o > 0; o >>= 1) {
        float t = __shfl_xor_sync(0xffffffffu, v, o);
        v = do_max ? fmaxf(v, t) : (v + t);
    }
    if (lane == 0) sred[wid] = v;
    __syncthreads();
    if (tid == 0) {
        float r = sred[0];
        #pragma unroll
        for (int w = 1; w < 8; ++w) r = do_max ? fmaxf(r, sred[w]) : (r + sred[w]);
        sred[8] = r;
    }
    __syncthreads();
    float r = sred[8];
    __syncthreads();
    return r;
}

// ---------------- warp-per-row RMSNorm + RoPE for Q -> fp16 hi/lo ----------------
// 256 thr = 8 warps; warp handles one (s,h) row; lane owns 8 contiguous d's.
// rotate_half via shfl_xor(.,4): lanes 0-3 <-> 4-7 exchange (d and d±32).
__global__ __launch_bounds__(256)
void q_norm_rope_kernel(const float* __restrict__ qkv,
                        const float* __restrict__ cosb, const float* __restrict__ sinb,
                        const float* __restrict__ qw,
                        __half* __restrict__ qh, __half* __restrict__ ql)
{
    const int warp = threadIdx.x >> 5, lane = threadIdx.x & 31;
    const int row = blockIdx.x * 8 + warp;     // 0..32767
    const int s = row >> 4, h = row & 15;

    const float* src = qkv + (size_t)s * NQKV + h * 512 + lane * 8;
    float4 a = *reinterpret_cast<const float4*>(src);
    float4 b = *reinterpret_cast<const float4*>(src + 4);
    float x[8] = { a.x, a.y, a.z, a.w, b.x, b.y, b.z, b.w };

    float ss = 0.f;
    #pragma unroll
    for (int e = 0; e < 8; ++e) ss += x[e] * x[e];
    #pragma unroll
    for (int o = 16; o > 0; o >>= 1) ss += __shfl_xor_sync(0xffffffffu, ss, o);
    const float r = rsqrtf(ss * (1.f / HD) + EPSV);

    float4 w0 = *reinterpret_cast<const float4*>(qw + lane * 8);
    float4 w1 = *reinterpret_cast<const float4*>(qw + lane * 8 + 4);
    float wv[8] = { w0.x, w0.y, w0.z, w0.w, w1.x, w1.y, w1.z, w1.w };

    float xn[8];
    #pragma unroll
    for (int e = 0; e < 8; ++e) xn[e] = x[e] * r * (1.f + wv[e]);

    float part[8];
    #pragma unroll
    for (int e = 0; e < 8; ++e) part[e] = __shfl_xor_sync(0xffffffffu, xn[e], 4);

    if (lane < 8) {   // d < 64: apply RoPE
        const float* cp = cosb + (size_t)s * RD + lane * 8;
        const float* sp = sinb + (size_t)s * RD + lane * 8;
        float4 c0 = *reinterpret_cast<const float4*>(cp);
        float4 c1 = *reinterpret_cast<const float4*>(cp + 4);
        float4 s0 = *reinterpret_cast<const float4*>(sp);
        float4 s1 = *reinterpret_cast<const float4*>(sp + 4);
        float cs[8] = { c0.x, c0.y, c0.z, c0.w, c1.x, c1.y, c1.z, c1.w };
        float sn[8] = { s0.x, s0.y, s0.z, s0.w, s1.x, s1.y, s1.z, s1.w };
        #pragma unroll
        for (int e = 0; e < 8; ++e) {
            float rot = (lane & 4) ? part[e] : -part[e];
            xn[e] = xn[e] * cs[e] + rot * sn[e];
        }
    }

    uint4 hh, ll;
    float lo[8];
    #pragma unroll
    for (int e = 0; e < 8; ++e) {
        __half hv = __float2half_rn(xn[e]);
        lo[e] = xn[e] - __half2float(hv);
        reinterpret_cast<__half*>(&hh)[e] = hv;
        reinterpret_cast<__half*>(&ll)[e] = __float2half_rn(lo[e]);
    }
    size_t idx = ((size_t)h * SEQ + s) * HD + lane * 8;
    *reinterpret_cast<uint4*>(qh + idx) = hh;
    *reinterpret_cast<uint4*>(ql + idx) = ll;
}

// ---------------- RMSNorm + RoPE for K; caches + fp16 planes ----------------
__global__ __launch_bounds__(256)
void kv_norm_rope_kernel(const float* __restrict__ qkv,
                         const float* __restrict__ cosb, const float* __restrict__ sinb,
                         const float* __restrict__ kw,
                         float* __restrict__ kcache, float* __restrict__ vcache,
                         __half* __restrict__ kplane, __half* __restrict__ vT)
{
    const int s = blockIdx.x, kv = blockIdx.y, d = threadIdx.x;
    const int lane = d & 31, wid = d >> 5;
    float x = qkv[(size_t)s * NQKV + 8192 + kv * 256 + d];
    float v = qkv[(size_t)s * NQKV + 8704 + kv * 256 + d];
    __shared__ float sred[9];
    __shared__ float xs[256];
    float r = blk_reduce(x * x, false, sred, d, lane, wid);
    r = rsqrtf(r * (1.f / HD) + EPSV);
    float xn = x * r * (1.f + kw[d]);
    xs[d] = xn;
    __syncthreads();
    float o = xn;
    if (d < RD) {
        float rot = (d < RD / 2) ? -xs[d + RD / 2] : xs[d - RD / 2];
        o = xn * cosb[(size_t)s * RD + d] + rot * sinb[(size_t)s * RD + d];
    }
    size_t cidx = ((size_t)kv * MAXS + s) * HD + d;
    kcache[cidx] = o;
    vcache[cidx] = v;
    kplane[((size_t)kv * SEQ + s) * HD + d] = __float2half_rn(o);
    vT[((size_t)kv * HD + d) * SEQ + s] = __float2half_rn(v);
}

// ---------------- zero pad caches rows SEQ..MAXS ----------------
__global__ void zero_pad_kernel(float* __restrict__ kcache, float* __restrict__ vcache)
{
    size_t idx = (size_t)blockIdx.x * blockDim.x + threadIdx.x;
    const size_t per_kv = (size_t)(MAXS - SEQ) * HD;
    if (idx >= (size_t)NKV * per_kv) return;
    size_t kv = idx / per_kv, rem = idx - kv * per_kv;
    size_t off = kv * (size_t)MAXS * HD + (size_t)SEQ * HD + rem;
    kcache[off] = 0.f;
    vcache[off] = 0.f;
}

// ---------------- causal softmax -> single fp16 P plane ----------------
__global__ __launch_bounds__(256)
void softmax_kernel(const float* __restrict__ scores, __half* __restrict__ ph)
{
    const int i = blockIdx.x, h = blockIdx.y, tid = threadIdx.x;
    const int lane = tid & 31, wid = tid >> 5;
    const float* row = scores + ((size_t)h * SEQ + i) * SEQ;
    __half* prh = ph + ((size_t)h * SEQ + i) * SEQ;
    const int n = i + 1;
    const int end = ((i >> 7) + 1) << 7;
    const int j0 = tid * 8;
    __shared__ float sred[9];

    float v[8];
    if (j0 < end) {
        float4 a = *reinterpret_cast<const float4*>(row + j0);
        float4 b = *reinterpret_cast<const float4*>(row + j0 + 4);
        v[0]=a.x; v[1]=a.y; v[2]=a.z; v[3]=a.w;
        v[4]=b.x; v[5]=b.y; v[6]=b.z; v[7]=b.w;
    } else {
        #pragma unroll
        for (int e = 0; e < 8; ++e) v[e] = -1e30f;
    }

    float m = -1e30f;
    #pragma unroll
    for (int e = 0; e < 8; ++e) if (j0 + e < n) m = fmaxf(m, v[e]);
    m = blk_reduce(m, true, sred, tid, lane, wid);

    float sum = 0.f;
    #pragma unroll
    for (int e = 0; e < 8; ++e) {
        float p = (j0 + e < n) ? __expf(v[e] - m) : 0.f;
        v[e] = p;
        sum += p;
    }
    sum = blk_reduce(sum, false, sred, tid, lane, wid);
    const float inv = 1.f / sum;

    if (j0 < end) {
        uint4 hh;
        hh.x = packh2(v[0]*inv, v[1]*inv);
        hh.y = packh2(v[2]*inv, v[3]*inv);
        hh.z = packh2(v[4]*inv, v[5]*inv);
        hh.w = packh2(v[6]*inv, v[7]*inv);
        *reinterpret_cast<uint4*>(prh + j0) = hh;
    }
}

// ---------------- gating: sum split-K partials, sigmoid gate -> fp16 plane -----
__global__ void gate_kernel(const float* __restrict__ attn, const float* __restrict__ attn2,
                            const float* __restrict__ qkv, __half* __restrict__ gh)
{
    size_t idx = (size_t)blockIdx.x * blockDim.x + threadIdx.x;
    if (idx >= (size_t)SEQ * NH * HD / 4) return;
    int s = (int)(idx >> 10);
    int r = (int)(idx & 1023);
    int h = r >> 6, dq = (r & 63) * 4;
    size_t aoff = ((size_t)h * SEQ + s) * HD + dq;
    float4 a = *reinterpret_cast<const float4*>(&attn[aoff]);
    if (s >= 1024) {
        float4 a2 = *reinterpret_cast<const float4*>(&attn2[aoff]);
        a.x += a2.x; a.y += a2.y; a.z += a2.z; a.w += a2.w;
    }
    float4 g = *reinterpret_cast<const float4*>(&qkv[(size_t)s * NQKV + h * 512 + 256 + dq]);
    float o0 = a.x * (1.f / (1.f + __expf(-g.x)));
    float o1 = a.y * (1.f / (1.f + __expf(-g.y)));
    float o2 = a.z * (1.f / (1.f + __expf(-g.z)));
    float o3 = a.w * (1.f / (1.f + __expf(-g.w)));
    uint2 hh = { packh2(o0, o1), packh2(o2, o3) };
    size_t o = (size_t)s * (NH * HD) + h * HD + dq;
    *reinterpret_cast<uint2*>(gh + o) = hh;
}

// ---------------- launch ----------------
extern "C" void kernel_launch(void* const* d_in, const int* in_sizes, int n_in,
                              void* d_out, int out_size)
{
    const float* hidden = (const float*)d_in[0];
    const float* cosb   = (const float*)d_in[1];
    const float* sinb   = (const float*)d_in[2];
    const float* q_w    = (const float*)d_in[3];
    const float* k_w    = (const float*)d_in[4];
    const float* v_w    = (const float*)d_in[5];
    const float* o_w    = (const float*)d_in[6];
    const float* qnw    = (const float*)d_in[7];
    const float* knw    = (const float*)d_in[8];

    float* hidden_out = (float*)d_out;
    float* kcache = hidden_out + (size_t)SEQ * HID;
    float* vcache = kcache + (size_t)NKV * MAXS * HD;

    float *qkv, *sc, *at, *at2;
    __half *hid, *wqkv, *owh, *kpl, *vT, *qh, *ql, *ph, *gt;
    cudaGetSymbolAddress((void**)&qkv, g_qkv);
    cudaGetSymbolAddress((void**)&sc, g_scores);
    cudaGetSymbolAddress((void**)&at, g_attn);
    cudaGetSymbolAddress((void**)&at2, g_attn2);
    cudaGetSymbolAddress((void**)&hid, g_hid);
    cudaGetSymbolAddress((void**)&wqkv, g_wqkv);
    cudaGetSymbolAddress((void**)&owh, g_ow);
    cudaGetSymbolAddress((void**)&qh, g_q_h);   cudaGetSymbolAddress((void**)&ql, g_q_l);
    cudaGetSymbolAddress((void**)&kpl, g_k);
    cudaGetSymbolAddress((void**)&vT, g_vT);
    cudaGetSymbolAddress((void**)&ph, g_p);
    cudaGetSymbolAddress((void**)&gt, g_gt);

    cudaFuncSetAttribute(gemm_1t_wide, cudaFuncAttributeMaxDynamicSharedMemorySize, 147456);
    cudaFuncSetAttribute(gemm_pv,      cudaFuncAttributeMaxDynamicSharedMemorySize, 147456);
    cudaFuncSetAttribute(gemm_2t,      cudaFuncAttributeMaxDynamicSharedMemorySize, 98304);

    dim3 blk(256);

    // 1) cache zero-pad
    zero_pad_kernel<<<(unsigned)(((size_t)NKV * (MAXS - SEQ) * HD + 255) / 256), blk>>>(kcache, vcache);
    // 2) all fp32->fp16 converts in one launch
    split_all_kernel<<<30720, blk>>>(hidden, q_w, k_w, v_w, o_w, hid, wqkv, owh);

    // 3) fused qkv projection [2048 x 9216], fp16 1-term wide
    gemm_1t_wide<<<dim3(NQKV/256, SEQ/128, 1), dim3(512), 147456>>>(
        (const uint16_t*)hid, (const uint16_t*)wqkv, qkv,
        HID, HID, HID, NQKV, 0, 0, 0, 1, 1.f, 0);

    // 4-5) norms + rope + caches (q_norm now warp-per-row)
    q_norm_rope_kernel<<<4096, blk>>>(qkv, cosb, sinb, qnw, qh, ql);
    kv_norm_rope_kernel<<<dim3(SEQ, NKV), blk>>>(qkv, cosb, sinb, knw,
                                                 kcache, vcache, kpl, vT);

    // 6) scores = Q @ K^T * scale (causal block skip), fp16 Q-2term / K-1term
    gemm_2t<<<dim3(SEQ/128, SEQ/128, NH), blk, 98304>>>(
        (const uint16_t*)qh, (const uint16_t*)ql, (const uint16_t*)kpl,
        sc, HD, HD, HD, SEQ,
        (long long)SEQ * HD, (long long)SEQ * HD, (long long)SEQ * SEQ, GROUPS,
        ATT_SCALE, 1);

    // 7) softmax -> single fp16 P plane
    softmax_kernel<<<dim3(SEQ, NH), blk>>>(sc, ph);

    // 8) attn = P @ V, causal split-K=2, big blocks first
    gemm_pv<<<dim3(1, 16, NH * 2), dim3(512), 147456>>>(
        (const uint16_t*)ph, (const uint16_t*)vT, at, at2,
        SEQ, SEQ, HD,
        (long long)SEQ * SEQ, (long long)HD * SEQ, (long long)SEQ * HD);

    // 9) gating (sums split-K partials) -> fp16 plane
    gate_kernel<<<(unsigned)(((size_t)SEQ * NH * HD / 4 + 255) / 256), blk>>>(at, at2, qkv, gt);

    // 10) hidden_out = gated @ o_w^T, fp16 1-term wide
    gemm_1t_wide<<<dim3(HID/256, SEQ/128, 1), dim3(512), 147456>>>(
        (const uint16_t*)gt, (const uint16_t*)owh, hidden_out,
        NH*HD, NH*HD, NH*HD, HID, 0, 0, 0, 1, 1.f, 0);
}

// round 17
// speedup vs baseline: 1.0965x; 1.0102x over previous
#include <cuda_runtime.h>
#include <cuda_bf16.h>
#include <cuda_fp16.h>
#include <cstdint>
#include <math.h>

// ---------------- problem constants ----------------
#define SEQ   2048
#define HID   2048
#define NH    16
#define NKV   2
#define HD    256
#define MAXS  4096
#define RD    64
#define GROUPS 8
#define ATT_SCALE 0.0625f
#define EPSV  1e-6f
#define NQKV  9216

// ---------------- scratch ----------------
__device__ __align__(1024) float g_qkv  [(size_t)SEQ * NQKV];
__device__ __align__(1024) float g_scores[(size_t)NH * SEQ * SEQ];
__device__ __align__(1024) float g_attn [(size_t)NH * SEQ * HD];
__device__ __align__(1024) float g_attn2[(size_t)NH * SEQ * HD];

__device__ __align__(1024) __half g_hid  [(size_t)SEQ * HID];
__device__ __align__(1024) __half g_wqkv [(size_t)NQKV * HID];
__device__ __align__(1024) __half g_ow   [(size_t)HID * NH*HD];
__device__ __align__(1024) __half g_q_h  [(size_t)NH*SEQ*HD], g_q_l[(size_t)NH*SEQ*HD];
__device__ __align__(1024) __half g_k    [(size_t)NKV*SEQ*HD];
__device__ __align__(1024) __half g_vT   [(size_t)NKV*HD*SEQ];
__device__ __align__(1024) __half g_p    [(size_t)NH*SEQ*SEQ];
__device__ __align__(1024) __half g_gt   [(size_t)SEQ * NH*HD];

// ---------------- PTX helpers ----------------
__device__ __forceinline__ uint32_t smem_u32(const void* p) {
    uint32_t a;
    asm("{ .reg .u64 t; cvta.to.shared.u64 t, %1; cvt.u32.u64 %0, t; }" : "=r"(a) : "l"(p));
    return a;
}
#define CP_ASYNC16(dst, src) \
    asm volatile("cp.async.cg.shared.global [%0], [%1], 16;" :: "r"(dst), "l"(src) : "memory")
#define CP_COMMIT() asm volatile("cp.async.commit_group;" ::: "memory")
#define CP_WAIT(n)  asm volatile("cp.async.wait_group %0;" :: "n"(n) : "memory")

#define LDSM_X4(r0, r1, r2, r3, addr) \
    asm volatile("ldmatrix.sync.aligned.m8n8.x4.shared.b16 {%0,%1,%2,%3}, [%4];" \
        : "=r"(r0), "=r"(r1), "=r"(r2), "=r"(r3) : "r"(addr))

#define MMA_F16(d, a, b0v, b1v) \
    asm volatile("mma.sync.aligned.m16n8k16.row.col.f32.f16.f16.f32 " \
        "{%0,%1,%2,%3}, {%4,%5,%6,%7}, {%8,%9}, {%0,%1,%2,%3};" \
        : "+f"((d)[0]), "+f"((d)[1]), "+f"((d)[2]), "+f"((d)[3]) \
        : "r"((a)[0]), "r"((a)[1]), "r"((a)[2]), "r"((a)[3]), "r"(b0v), "r"(b1v))

// ---------------- pack helpers ----------------
__device__ __forceinline__ uint32_t packh2(float a, float b) {
    __half2 h = __floats2half2_rn(a, b);
    return *reinterpret_cast<uint32_t*>(&h);
}
__device__ __forceinline__ uint4 pack8(const float4& a, const float4& b) {
    uint4 r;
    r.x = packh2(a.x, a.y); r.y = packh2(a.z, a.w);
    r.z = packh2(b.x, b.y); r.w = packh2(b.z, b.w);
    return r;
}

// ---------------- fp16 1-term GEMM, 128x256 tile, 512 thr, 3-stage (frozen) ----
__global__ __launch_bounds__(512, 1)
void gemm_1t_wide(const uint16_t* __restrict__ A, const uint16_t* __restrict__ B,
                  float* __restrict__ C,
                  int K, int lda, int ldb, int ldc,
                  long long sA, long long sB, long long sC, int bDiv,
                  float alpha, int mode)
{
    constexpr uint32_t STG = 49152u;

    const int bx = blockIdx.x, by = blockIdx.y, bz = blockIdx.z;
    const int Keff = (mode == 2) ? min(K, (by + 1) * 128) : K;
    const int nch = Keff >> 6;

    extern __shared__ char smem[];
    const uint32_t sb = smem_u32(smem);

    const uint16_t* pA = A + (size_t)bz * sA;
    const uint16_t* pB = B + (size_t)(bz / bDiv) * sB;
    const int rm = by * 128, rn = bx * 256;
    const int tid = threadIdx.x, lane = tid & 31, wid = tid >> 5;
    const int wm = wid >> 2, wn = wid & 3;

    float acc[2][8][4];
    #pragma unroll
    for (int mt = 0; mt < 2; ++mt)
        #pragma unroll
        for (int nt = 0; nt < 8; ++nt)
            #pragma unroll
            for (int r = 0; r < 4; ++r) acc[mt][nt][r] = 0.f;

    auto issue = [&](int ch) {
        const uint32_t dbase = sb + (uint32_t)(ch % 3) * STG;
        const int kt = ch << 6;
        #pragma unroll
        for (int i = 0; i < 2; ++i) {
            const int u = tid + i * 512;
            const int r = u >> 3, c = u & 7;
            const uint16_t* s = pA + (size_t)(rm + r) * lda + kt + c * 8;
            const uint32_t d = dbase + (uint32_t)(r * 128 + ((c * 16) ^ ((r & 7) << 4)));
            CP_ASYNC16(d, (const void*)s);
        }
        #pragma unroll
        for (int i = 0; i < 4; ++i) {
            const int u = tid + i * 512;
            const int r = u >> 3, c = u & 7;
            const uint16_t* s = pB + (size_t)(rn + r) * ldb + kt + c * 8;
            const uint32_t d = dbase + 16384u + (uint32_t)(r * 128 + ((c * 16) ^ ((r & 7) << 4)));
            CP_ASYNC16(d, (const void*)s);
        }
        CP_COMMIT();
    };

    issue(0);
    if (nch > 1) issue(1);
    for (int ch = 0; ch < nch; ++ch) {
        if (ch + 1 < nch) { CP_WAIT(1); }
        else              { CP_WAIT(0); }
        __syncthreads();
        if (ch + 2 < nch) issue(ch + 2);

        const uint32_t b0 = sb + (uint32_t)(ch % 3) * STG;

        #pragma unroll
        for (int ks = 0; ks < 4; ++ks) {
            const uint32_t colk = (uint32_t)(ks * 32 + ((lane >> 4) << 4));
            uint32_t ah[2][4], bh[4][4];
            #pragma unroll
            for (int mt = 0; mt < 2; ++mt) {
                const int row = wm * 32 + mt * 16 + (lane & 15);
                const uint32_t a0 = b0 + (uint32_t)(row * 128) + (colk ^ ((row & 7) << 4));
                LDSM_X4(ah[mt][0], ah[mt][1], ah[mt][2], ah[mt][3], a0);
            }
            #pragma unroll
            for (int pr = 0; pr < 4; ++pr) {
                const int row = wn * 64 + pr * 16 + (lane & 15);
                const uint32_t a0 = b0 + 16384u + (uint32_t)(row * 128) + (colk ^ ((row & 7) << 4));
                LDSM_X4(bh[pr][0], bh[pr][1], bh[pr][2], bh[pr][3], a0);
            }
            #pragma unroll
            for (int mt = 0; mt < 2; ++mt) {
                #pragma unroll
                for (int nt = 0; nt < 8; ++nt) {
                    const uint32_t b0v = bh[nt >> 1][nt & 1];
                    const uint32_t b1v = bh[nt >> 1][(nt & 1) + 2];
                    MMA_F16(acc[mt][nt], ah[mt], b0v, b1v);
                }
            }
        }
    }

    float* pC = C + (size_t)bz * sC;
    #pragma unroll
    for (int mt = 0; mt < 2; ++mt) {
        #pragma unroll
        for (int nt = 0; nt < 8; ++nt) {
            const int row = rm + wm * 32 + mt * 16 + (lane >> 2);
            const int col = rn + wn * 64 + nt * 8 + (lane & 3) * 2;
            float2 v0 = { acc[mt][nt][0] * alpha, acc[mt][nt][1] * alpha };
            float2 v1 = { acc[mt][nt][2] * alpha, acc[mt][nt][3] * alpha };
            *reinterpret_cast<float2*>(&pC[(size_t)row * ldc + col])       = v0;
            *reinterpret_cast<float2*>(&pC[(size_t)(row + 8) * ldc + col]) = v1;
        }
    }
}

// ---------------- PV split-K GEMM (causal, split-K=2, by reversed; frozen) ------
__global__ __launch_bounds__(512, 1)
void gemm_pv(const uint16_t* __restrict__ A, const uint16_t* __restrict__ B,
             float* __restrict__ C, float* __restrict__ C2,
             int lda, int ldb, int ldc,
             long long sA, long long sB, long long sC)
{
    constexpr uint32_t STG = 49152u;

    const int bx = blockIdx.x;
    const int by = (int)gridDim.y - 1 - (int)blockIdx.y;
    const int bz = blockIdx.z;
    const int head = bz >> 1, kz = bz & 1;

    const int Keff = min(SEQ, (by + 1) * 128);
    const int kbeg = kz << 10;
    const int kend = min(Keff, kbeg + 1024);
    if (kbeg >= kend) return;
    const int ch0 = kbeg >> 6;
    const int nch = (kend - kbeg) >> 6;

    extern __shared__ char smem[];
    const uint32_t sb = smem_u32(smem);

    const uint16_t* pA = A + (size_t)head * sA;
    const uint16_t* pB = B + (size_t)(head / GROUPS) * sB;
    const int rm = by * 128, rn = bx * 256;
    const int tid = threadIdx.x, lane = tid & 31, wid = tid >> 5;
    const int wm = wid >> 2, wn = wid & 3;

    float acc[2][8][4];
    #pragma unroll
    for (int mt = 0; mt < 2; ++mt)
        #pragma unroll
        for (int nt = 0; nt < 8; ++nt)
            #pragma unroll
            for (int r = 0; r < 4; ++r) acc[mt][nt][r] = 0.f;

    auto issue = [&](int cc) {
        const uint32_t dbase = sb + (uint32_t)(cc % 3) * STG;
        const int kt = (ch0 + cc) << 6;
        #pragma unroll
        for (int i = 0; i < 2; ++i) {
            const int u = tid + i * 512;
            const int r = u >> 3, c = u & 7;
            const uint16_t* s = pA + (size_t)(rm + r) * lda + kt + c * 8;
            const uint32_t d = dbase + (uint32_t)(r * 128 + ((c * 16) ^ ((r & 7) << 4)));
            CP_ASYNC16(d, (const void*)s);
        }
        #pragma unroll
        for (int i = 0; i < 4; ++i) {
            const int u = tid + i * 512;
            const int r = u >> 3, c = u & 7;
            const uint16_t* s = pB + (size_t)(rn + r) * ldb + kt + c * 8;
            const uint32_t d = dbase + 16384u + (uint32_t)(r * 128 + ((c * 16) ^ ((r & 7) << 4)));
            CP_ASYNC16(d, (const void*)s);
        }
        CP_COMMIT();
    };

    issue(0);
    if (nch > 1) issue(1);
    for (int cc = 0; cc < nch; ++cc) {
        if (cc + 1 < nch) { CP_WAIT(1); }
        else              { CP_WAIT(0); }
        __syncthreads();
        if (cc + 2 < nch) issue(cc + 2);

        const uint32_t b0 = sb + (uint32_t)(cc % 3) * STG;

        #pragma unroll
        for (int ks = 0; ks < 4; ++ks) {
            const uint32_t colk = (uint32_t)(ks * 32 + ((lane >> 4) << 4));
            uint32_t ah[2][4], bh[4][4];
            #pragma unroll
            for (int mt = 0; mt < 2; ++mt) {
                const int row = wm * 32 + mt * 16 + (lane & 15);
                const uint32_t a0 = b0 + (uint32_t)(row * 128) + (colk ^ ((row & 7) << 4));
                LDSM_X4(ah[mt][0], ah[mt][1], ah[mt][2], ah[mt][3], a0);
            }
            #pragma unroll
            for (int pr = 0; pr < 4; ++pr) {
                const int row = wn * 64 + pr * 16 + (lane & 15);
                const uint32_t a0 = b0 + 16384u + (uint32_t)(row * 128) + (colk ^ ((row & 7) << 4));
                LDSM_X4(bh[pr][0], bh[pr][1], bh[pr][2], bh[pr][3], a0);
            }
            #pragma unroll
            for (int mt = 0; mt < 2; ++mt) {
                #pragma unroll
                for (int nt = 0; nt < 8; ++nt) {
                    const uint32_t b0v = bh[nt >> 1][nt & 1];
                    const uint32_t b1v = bh[nt >> 1][(nt & 1) + 2];
                    MMA_F16(acc[mt][nt], ah[mt], b0v, b1v);
                }
            }
        }
    }

    float* pC = (kz ? C2 : C) + (size_t)head * sC;
    #pragma unroll
    for (int mt = 0; mt < 2; ++mt) {
        #pragma unroll
        for (int nt = 0; nt < 8; ++nt) {
            const int row = rm + wm * 32 + mt * 16 + (lane >> 2);
            const int col = rn + wn * 64 + nt * 8 + (lane & 3) * 2;
            float2 v0 = { acc[mt][nt][0], acc[mt][nt][1] };
            float2 v1 = { acc[mt][nt][2], acc[mt][nt][3] };
            *reinterpret_cast<float2*>(&pC[(size_t)row * ldc + col])       = v0;
            *reinterpret_cast<float2*>(&pC[(size_t)(row + 8) * ldc + col]) = v1;
        }
    }
}

// ---------------- fp16 2-term GEMM, 128x128 tile, 256 thr (scores; frozen) -----
__global__ __launch_bounds__(256, 2)
void gemm_2t(const uint16_t* __restrict__ Ah, const uint16_t* __restrict__ Al,
             const uint16_t* __restrict__ Bh,
             float* __restrict__ C,
             int K, int lda, int ldb, int ldc,
             long long sA, long long sB, long long sC, int bDiv,
             float alpha, int mode)
{
    constexpr uint32_t STG = 49152u;

    const int bx = blockIdx.x, by = blockIdx.y, bz = blockIdx.z;
    if (mode == 1 && bx > by) return;
    const int Keff = (mode == 2) ? min(K, (by + 1) * 128) : K;
    const int nch = Keff >> 6;

    extern __shared__ char smem[];
    const uint32_t sb = smem_u32(smem);

    const uint16_t* pAh = Ah + (size_t)bz * sA;
    const uint16_t* pAl = Al + (size_t)bz * sA;
    const uint16_t* pB  = Bh + (size_t)(bz / bDiv) * sB;
    const int rm = by * 128, rn = bx * 128;

    const int tid = threadIdx.x, lane = tid & 31, wid = tid >> 5;
    const int wm = wid >> 1, wn = wid & 1;

    float acc[2][8][4];
    #pragma unroll
    for (int mt = 0; mt < 2; ++mt)
        #pragma unroll
        for (int nt = 0; nt < 8; ++nt)
            #pragma unroll
            for (int r = 0; r < 4; ++r) acc[mt][nt][r] = 0.f;

    auto issue = [&](int ch) {
        const uint32_t dbase = sb + (uint32_t)(ch & 1) * STG;
        const int kt = ch << 6;
        #pragma unroll
        for (int p = 0; p < 3; ++p) {
            const uint16_t* sp = (p == 0) ? pAh : (p == 1) ? pAl : pB;
            const int rbase = (p < 2) ? rm : rn;
            const int ld = (p < 2) ? lda : ldb;
            #pragma unroll
            for (int i = 0; i < 4; ++i) {
                const int u = tid + i * 256;
                const int r = u >> 3, c = u & 7;
                const uint16_t* s = sp + (size_t)(rbase + r) * ld + kt + c * 8;
                const uint32_t d = dbase + (uint32_t)(p * 16384 + r * 128 +
                                   ((c * 16) ^ ((r & 7) << 4)));
                CP_ASYNC16(d, (const void*)s);
            }
        }
        CP_COMMIT();
    };

    issue(0);
    for (int ch = 0; ch < nch; ++ch) {
        CP_WAIT(0);
        __syncthreads();
        if (ch + 1 < nch) issue(ch + 1);

        const uint32_t b0 = sb + (uint32_t)(ch & 1) * STG;

        #pragma unroll
        for (int ks = 0; ks < 4; ++ks) {
            const uint32_t colk = (uint32_t)(ks * 32 + ((lane >> 4) << 4));
            uint32_t ah[2][4], alr[2][4], bh[4][4];
            #pragma unroll
            for (int mt = 0; mt < 2; ++mt) {
                const int row = wm * 32 + mt * 16 + (lane & 15);
                const uint32_t a0 = b0 + (uint32_t)(row * 128) + (colk ^ ((row & 7) << 4));
                LDSM_X4(ah [mt][0], ah [mt][1], ah [mt][2], ah [mt][3], a0);
                LDSM_X4(alr[mt][0], alr[mt][1], alr[mt][2], alr[mt][3], a0 + 16384u);
            }
            #pragma unroll
            for (int pr = 0; pr < 4; ++pr) {
                const int row = wn * 64 + pr * 16 + (lane & 15);
                const uint32_t a0 = b0 + 32768u + (uint32_t)(row * 128) + (colk ^ ((row & 7) << 4));
                LDSM_X4(bh[pr][0], bh[pr][1], bh[pr][2], bh[pr][3], a0);
            }
            #pragma unroll
            for (int term = 0; term < 2; ++term) {
                #pragma unroll
                for (int mt = 0; mt < 2; ++mt) {
                    #pragma unroll
                    for (int nt = 0; nt < 8; ++nt) {
                        const uint32_t* af = (term == 1) ? alr[mt] : ah[mt];
                        const uint32_t b0v = bh[nt >> 1][nt & 1];
                        const uint32_t b1v = bh[nt >> 1][(nt & 1) + 2];
                        MMA_F16(acc[mt][nt], af, b0v, b1v);
                    }
                }
            }
        }
    }

    float* pC = C + (size_t)bz * sC;
    #pragma unroll
    for (int mt = 0; mt < 2; ++mt) {
        #pragma unroll
        for (int nt = 0; nt < 8; ++nt) {
            const int row = rm + wm * 32 + mt * 16 + (lane >> 2);
            const int col = rn + wn * 64 + nt * 8 + (lane & 3) * 2;
            float2 v0 = { acc[mt][nt][0] * alpha, acc[mt][nt][1] * alpha };
            float2 v1 = { acc[mt][nt][2] * alpha, acc[mt][nt][3] * alpha };
            *reinterpret_cast<float2*>(&pC[(size_t)row * ldc + col])       = v0;
            *reinterpret_cast<float2*>(&pC[(size_t)(row + 8) * ldc + col]) = v1;
        }
    }
}

// ---------------- fused fp32->fp16 convert, 8 floats/thread, MLP4 ----------------
// oct (8-float) boundaries: hid 524288 | qw 2621440 | kw 2752512 | vw 2883584 | ow 3932160
#define NOCT 3932160u
#define SPLIT_STRIDE 983040u
__global__ __launch_bounds__(256)
void split_all_kernel(const float* __restrict__ hid4, const float* __restrict__ qw,
                      const float* __restrict__ kw, const float* __restrict__ vw,
                      const float* __restrict__ ow,
                      __half* __restrict__ hidh, __half* __restrict__ wqkv,
                      __half* __restrict__ owh)
{
    const uint32_t i0 = blockIdx.x * 256u + threadIdx.x;   // 0..983039
    #pragma unroll
    for (int k = 0; k < 4; ++k) {
        const uint32_t o = i0 + (uint32_t)k * SPLIT_STRIDE;
        const float* src; uint32_t loc; __half* dst;
        if (o < 524288u)       { src = hid4; loc = o;            dst = hidh; }
        else if (o < 2621440u) { src = qw;   loc = o - 524288u;  dst = wqkv; }
        else if (o < 2752512u) { src = kw;   loc = o - 2621440u; dst = wqkv + 16777216u; }
        else if (o < 2883584u) { src = vw;   loc = o - 2752512u; dst = wqkv + 17825792u; }
        else                   { src = ow;   loc = o - 2883584u; dst = owh; }
        float4 a = reinterpret_cast<const float4*>(src)[(size_t)loc * 2];
        float4 b = reinterpret_cast<const float4*>(src)[(size_t)loc * 2 + 1];
        reinterpret_cast<uint4*>(dst)[loc] = pack8(a, b);
    }
}

// ---------------- block reduce (kv_norm / softmax) ----------------
__device__ __forceinline__ float blk_reduce(float v, bool do_max, float* sred,
                                            int tid, int lane, int wid) {
    #pragma unroll
    for (int o = 16; o > 0; o >>= 1) {
        float t = __shfl_xor_sync(0xffffffffu, v, o);
        v = do_max ? fmaxf(v, t) : (v + t);
    }
    if (lane == 0) sred[wid] = v;
    __syncthreads();
    if (tid == 0) {
        float r = sred[0];
        #pragma unroll
        for (int w = 1; w < 8; ++w) r = do_max ? fmaxf(r, sred[w]) : (r + sred[w]);
        sred[8] = r;
    }
    __syncthreads();
    float r = sred[8];
    __syncthreads();
    return r;
}

// ---------------- warp-per-row RMSNorm + RoPE for Q -> fp16 hi/lo ----------------
__global__ __launch_bounds__(256)
void q_norm_rope_kernel(const float* __restrict__ qkv,
                        const float* __restrict__ cosb, const float* __restrict__ sinb,
                        const float* __restrict__ qw,
                        __half* __restrict__ qh, __half* __restrict__ ql)
{
    const int warp = threadIdx.x >> 5, lane = threadIdx.x & 31;
    const int row = blockIdx.x * 8 + warp;
    const int s = row >> 4, h = row & 15;

    const float* src = qkv + (size_t)s * NQKV + h * 512 + lane * 8;
    float4 a = *reinterpret_cast<const float4*>(src);
    float4 b = *reinterpret_cast<const float4*>(src + 4);
    float x[8] = { a.x, a.y, a.z, a.w, b.x, b.y, b.z, b.w };

    float ss = 0.f;
    #pragma unroll
    for (int e = 0; e < 8; ++e) ss += x[e] * x[e];
    #pragma unroll
    for (int o = 16; o > 0; o >>= 1) ss += __shfl_xor_sync(0xffffffffu, ss, o);
    const float r = rsqrtf(ss * (1.f / HD) + EPSV);

    float4 w0 = *reinterpret_cast<const float4*>(qw + lane * 8);
    float4 w1 = *reinterpret_cast<const float4*>(qw + lane * 8 + 4);
    float wv[8] = { w0.x, w0.y, w0.z, w0.w, w1.x, w1.y, w1.z, w1.w };

    float xn[8];
    #pragma unroll
    for (int e = 0; e < 8; ++e) xn[e] = x[e] * r * (1.f + wv[e]);

    float part[8];
    #pragma unroll
    for (int e = 0; e < 8; ++e) part[e] = __shfl_xor_sync(0xffffffffu, xn[e], 4);

    if (lane < 8) {
        const float* cp = cosb + (size_t)s * RD + lane * 8;
        const float* sp = sinb + (size_t)s * RD + lane * 8;
        float4 c0 = *reinterpret_cast<const float4*>(cp);
        float4 c1 = *reinterpret_cast<const float4*>(cp + 4);
        float4 s0 = *reinterpret_cast<const float4*>(sp);
        float4 s1 = *reinterpret_cast<const float4*>(sp + 4);
        float cs[8] = { c0.x, c0.y, c0.z, c0.w, c1.x, c1.y, c1.z, c1.w };
        float sn[8] = { s0.x, s0.y, s0.z, s0.w, s1.x, s1.y, s1.z, s1.w };
        #pragma unroll
        for (int e = 0; e < 8; ++e) {
            float rot = (lane & 4) ? part[e] : -part[e];
            xn[e] = xn[e] * cs[e] + rot * sn[e];
        }
    }

    uint4 hh, ll;
    float lo[8];
    #pragma unroll
    for (int e = 0; e < 8; ++e) {
        __half hv = __float2half_rn(xn[e]);
        lo[e] = xn[e] - __half2float(hv);
        reinterpret_cast<__half*>(&hh)[e] = hv;
        reinterpret_cast<__half*>(&ll)[e] = __float2half_rn(lo[e]);
    }
    size_t idx = ((size_t)h * SEQ + s) * HD + lane * 8;
    *reinterpret_cast<uint4*>(qh + idx) = hh;
    *reinterpret_cast<uint4*>(ql + idx) = ll;
}

// ---------------- RMSNorm + RoPE for K; caches + fp16 planes ----------------
__global__ __launch_bounds__(256)
void kv_norm_rope_kernel(const float* __restrict__ qkv,
                         const float* __restrict__ cosb, const float* __restrict__ sinb,
                         const float* __restrict__ kw,
                         float* __restrict__ kcache, float* __restrict__ vcache,
                         __half* __restrict__ kplane, __half* __restrict__ vT)
{
    const int s = blockIdx.x, kv = blockIdx.y, d = threadIdx.x;
    const int lane = d & 31, wid = d >> 5;
    float x = qkv[(size_t)s * NQKV + 8192 + kv * 256 + d];
    float v = qkv[(size_t)s * NQKV + 8704 + kv * 256 + d];
    __shared__ float sred[9];
    __shared__ float xs[256];
    float r = blk_reduce(x * x, false, sred, d, lane, wid);
    r = rsqrtf(r * (1.f / HD) + EPSV);
    float xn = x * r * (1.f + kw[d]);
    xs[d] = xn;
    __syncthreads();
    float o = xn;
    if (d < RD) {
        float rot = (d < RD / 2) ? -xs[d + RD / 2] : xs[d - RD / 2];
        o = xn * cosb[(size_t)s * RD + d] + rot * sinb[(size_t)s * RD + d];
    }
    size_t cidx = ((size_t)kv * MAXS + s) * HD + d;
    kcache[cidx] = o;
    vcache[cidx] = v;
    kplane[((size_t)kv * SEQ + s) * HD + d] = __float2half_rn(o);
    vT[((size_t)kv * HD + d) * SEQ + s] = __float2half_rn(v);
}

// ---------------- zero pad caches rows SEQ..MAXS ----------------
__global__ void zero_pad_kernel(float* __restrict__ kcache, float* __restrict__ vcache)
{
    size_t idx = (size_t)blockIdx.x * blockDim.x + threadIdx.x;
    const size_t per_kv = (size_t)(MAXS - SEQ) * HD;
    if (idx >= (size_t)NKV * per_kv) return;
    size_t kv = idx / per_kv, rem = idx - kv * per_kv;
    size_t off = kv * (size_t)MAXS * HD + (size_t)SEQ * HD + rem;
    kcache[off] = 0.f;
    vcache[off] = 0.f;
}

// ---------------- causal softmax -> single fp16 P plane ----------------
__global__ __launch_bounds__(256)
void softmax_kernel(const float* __restrict__ scores, __half* __restrict__ ph)
{
    const int i = blockIdx.x, h = blockIdx.y, tid = threadIdx.x;
    const int lane = tid & 31, wid = tid >> 5;
    const float* row = scores + ((size_t)h * SEQ + i) * SEQ;
    __half* prh = ph + ((size_t)h * SEQ + i) * SEQ;
    const int n = i + 1;
    const int end = ((i >> 7) + 1) << 7;
    const int j0 = tid * 8;
    __shared__ float sred[9];

    float v[8];
    if (j0 < end) {
        float4 a = *reinterpret_cast<const float4*>(row + j0);
        float4 b = *reinterpret_cast<const float4*>(row + j0 + 4);
        v[0]=a.x; v[1]=a.y; v[2]=a.z; v[3]=a.w;
        v[4]=b.x; v[5]=b.y; v[6]=b.z; v[7]=b.w;
    } else {
        #pragma unroll
        for (int e = 0; e < 8; ++e) v[e] = -1e30f;
    }

    float m = -1e30f;
    #pragma unroll
    for (int e = 0; e < 8; ++e) if (j0 + e < n) m = fmaxf(m, v[e]);
    m = blk_reduce(m, true, sred, tid, lane, wid);

    float sum = 0.f;
    #pragma unroll
    for (int e = 0; e < 8; ++e) {
        float p = (j0 + e < n) ? __expf(v[e] - m) : 0.f;
        v[e] = p;
        sum += p;
    }
    sum = blk_reduce(sum, false, sred, tid, lane, wid);
    const float inv = 1.f / sum;

    if (j0 < end) {
        uint4 hh;
        hh.x = packh2(v[0]*inv, v[1]*inv);
        hh.y = packh2(v[2]*inv, v[3]*inv);
        hh.z = packh2(v[4]*inv, v[5]*inv);
        hh.w = packh2(v[6]*inv, v[7]*inv);
        *reinterpret_cast<uint4*>(prh + j0) = hh;
    }
}

// ---------------- gating: 8 floats/thread, sum split-K, sigmoid -> fp16 ---------
__global__ __launch_bounds__(256)
void gate_kernel(const float* __restrict__ attn, const float* __restrict__ attn2,
                 const float* __restrict__ qkv, __half* __restrict__ gh)
{
    size_t idx = (size_t)blockIdx.x * blockDim.x + threadIdx.x;   // oct index
    if (idx >= (size_t)SEQ * NH * HD / 8) return;
    int s = (int)(idx >> 9);
    int r = (int)(idx & 511);
    int h = r >> 5, d8 = (r & 31) * 8;
    size_t aoff = ((size_t)h * SEQ + s) * HD + d8;
    float4 a0 = *reinterpret_cast<const float4*>(&attn[aoff]);
    float4 a1 = *reinterpret_cast<const float4*>(&attn[aoff + 4]);
    if (s >= 1024) {
        float4 b0 = *reinterpret_cast<const float4*>(&attn2[aoff]);
        float4 b1 = *reinterpret_cast<const float4*>(&attn2[aoff + 4]);
        a0.x += b0.x; a0.y += b0.y; a0.z += b0.z; a0.w += b0.w;
        a1.x += b1.x; a1.y += b1.y; a1.z += b1.z; a1.w += b1.w;
    }
    const float* gp = qkv + (size_t)s * NQKV + h * 512 + 256 + d8;
    float4 g0 = *reinterpret_cast<const float4*>(gp);
    float4 g1 = *reinterpret_cast<const float4*>(gp + 4);
    float o[8];
    o[0] = a0.x * (1.f / (1.f + __expf(-g0.x)));
    o[1] = a0.y * (1.f / (1.f + __expf(-g0.y)));
    o[2] = a0.z * (1.f / (1.f + __expf(-g0.z)));
    o[3] = a0.w * (1.f / (1.f + __expf(-g0.w)));
    o[4] = a1.x * (1.f / (1.f + __expf(-g1.x)));
    o[5] = a1.y * (1.f / (1.f + __expf(-g1.y)));
    o[6] = a1.z * (1.f / (1.f + __expf(-g1.z)));
    o[7] = a1.w * (1.f / (1.f + __expf(-g1.w)));
    uint4 hh;
    hh.x = packh2(o[0], o[1]); hh.y = packh2(o[2], o[3]);
    hh.z = packh2(o[4], o[5]); hh.w = packh2(o[6], o[7]);
    *reinterpret_cast<uint4*>(gh + (size_t)s * (NH * HD) + h * HD + d8) = hh;
}

// ---------------- launch ----------------
extern "C" void kernel_launch(void* const* d_in, const int* in_sizes, int n_in,
                              void* d_out, int out_size)
{
    const float* hidden = (const float*)d_in[0];
    const float* cosb   = (const float*)d_in[1];
    const float* sinb   = (const float*)d_in[2];
    const float* q_w    = (const float*)d_in[3];
    const float* k_w    = (const float*)d_in[4];
    const float* v_w    = (const float*)d_in[5];
    const float* o_w    = (const float*)d_in[6];
    const float* qnw    = (const float*)d_in[7];
    const float* knw    = (const float*)d_in[8];

    float* hidden_out = (float*)d_out;
    float* kcache = hidden_out + (size_t)SEQ * HID;
    float* vcache = kcache + (size_t)NKV * MAXS * HD;

    float *qkv, *sc, *at, *at2;
    __half *hid, *wqkv, *owh, *kpl, *vT, *qh, *ql, *ph, *gt;
    cudaGetSymbolAddress((void**)&qkv, g_qkv);
    cudaGetSymbolAddress((void**)&sc, g_scores);
    cudaGetSymbolAddress((void**)&at, g_attn);
    cudaGetSymbolAddress((void**)&at2, g_attn2);
    cudaGetSymbolAddress((void**)&hid, g_hid);
    cudaGetSymbolAddress((void**)&wqkv, g_wqkv);
    cudaGetSymbolAddress((void**)&owh, g_ow);
    cudaGetSymbolAddress((void**)&qh, g_q_h);   cudaGetSymbolAddress((void**)&ql, g_q_l);
    cudaGetSymbolAddress((void**)&kpl, g_k);
    cudaGetSymbolAddress((void**)&vT, g_vT);
    cudaGetSymbolAddress((void**)&ph, g_p);
    cudaGetSymbolAddress((void**)&gt, g_gt);

    cudaFuncSetAttribute(gemm_1t_wide, cudaFuncAttributeMaxDynamicSharedMemorySize, 147456);
    cudaFuncSetAttribute(gemm_pv,      cudaFuncAttributeMaxDynamicSharedMemorySize, 147456);
    cudaFuncSetAttribute(gemm_2t,      cudaFuncAttributeMaxDynamicSharedMemorySize, 98304);

    dim3 blk(256);

    // 1) cache zero-pad
    zero_pad_kernel<<<(unsigned)(((size_t)NKV * (MAXS - SEQ) * HD + 255) / 256), blk>>>(kcache, vcache);
    // 2) all fp32->fp16 converts (8 floats/thread, MLP4)
    split_all_kernel<<<3840, blk>>>(hidden, q_w, k_w, v_w, o_w, hid, wqkv, owh);

    // 3) fused qkv projection [2048 x 9216]
    gemm_1t_wide<<<dim3(NQKV/256, SEQ/128, 1), dim3(512), 147456>>>(
        (const uint16_t*)hid, (const uint16_t*)wqkv, qkv,
        HID, HID, HID, NQKV, 0, 0, 0, 1, 1.f, 0);

    // 4-5) norms + rope + caches
    q_norm_rope_kernel<<<4096, blk>>>(qkv, cosb, sinb, qnw, qh, ql);
    kv_norm_rope_kernel<<<dim3(SEQ, NKV), blk>>>(qkv, cosb, sinb, knw,
                                                 kcache, vcache, kpl, vT);

    // 6) scores = Q @ K^T * scale (causal block skip)
    gemm_2t<<<dim3(SEQ/128, SEQ/128, NH), blk, 98304>>>(
        (const uint16_t*)qh, (const uint16_t*)ql, (const uint16_t*)kpl,
        sc, HD, HD, HD, SEQ,
        (long long)SEQ * HD, (long long)SEQ * HD, (long long)SEQ * SEQ, GROUPS,
        ATT_SCALE, 1);

    // 7) softmax -> single fp16 P plane
    softmax_kernel<<<dim3(SEQ, NH), blk>>>(sc, ph);

    // 8) attn = P @ V, causal split-K=2, big blocks first
    gemm_pv<<<dim3(1, 16, NH * 2), dim3(512), 147456>>>(
        (const uint16_t*)ph, (const uint16_t*)vT, at, at2,
        SEQ, SEQ, HD,
        (long long)SEQ * SEQ, (long long)HD * SEQ, (long long)SEQ * HD);

    // 9) gating (sums split-K partials) -> fp16 plane (8 floats/thread)
    gate_kernel<<<(unsigned)(((size_t)SEQ * NH * HD / 8 + 255) / 256), blk>>>(at, at2, qkv, gt);

    // 10) hidden_out = gated @ o_w^T
    gemm_1t_wide<<<dim3(HID/256, SEQ/128, 1), dim3(512), 147456>>>(
        (const uint16_t*)gt, (const uint16_t*)owh, hidden_out,
        NH*HD, NH*HD, NH*HD, HID, 0, 0, 0, 1, 1.f, 0);
}